// round 1
// baseline (speedup 1.0000x reference)
#include <cuda_runtime.h>
#include <math.h>
#include <stdint.h>

#define N_NODES 50000
#define N_EDGES 800000
#define IN_CH   128
#define F1      256   // heads*out layer1
#define F2      64
#define H1      4
#define H2      1

// ---------------- scratch (device globals; no allocation allowed) -----------
__device__ float    g_q1[N_NODES * F1];
__device__ float    g_k1[N_NODES * F1];
__device__ float    g_v1[N_NODES * F1];
__device__ float    g_r1[N_NODES * F1];
__device__ float    g_out1[N_NODES * F1];
__device__ float    g_h[N_NODES * F1];
__device__ float    g_alpha1[N_EDGES * H1];
__device__ unsigned g_amax1[N_NODES * H1];
__device__ float    g_den1[N_NODES * H1];

__device__ float    g_q2[N_NODES * F2];
__device__ float    g_k2[N_NODES * F2];
__device__ float    g_v2[N_NODES * F2];
__device__ float    g_r2[N_NODES * F2];
__device__ float    g_out2[N_NODES * F2];
__device__ float    g_y2[N_NODES * F2];
__device__ float    g_alpha2[N_EDGES * H2];
__device__ unsigned g_amax2[N_NODES * H2];
__device__ float    g_den2[N_NODES * H2];

// monotone float <-> uint mapping for atomicMax on floats
__device__ __forceinline__ unsigned fkey(float f) {
    unsigned b = __float_as_uint(f);
    return (b & 0x80000000u) ? ~b : (b | 0x80000000u);
}
__device__ __forceinline__ float funkey(unsigned u) {
    unsigned b = (u & 0x80000000u) ? (u & 0x7FFFFFFFu) : ~u;
    return __uint_as_float(b);
}

// fkey(-inf) = ~0xFF800000 = 0x007FFFFF
#define NEG_INF_KEY 0x007FFFFFu

// ---------------- init: zero accumulators, set -inf maxes -------------------
__global__ void init_kernel() {
    int stride = gridDim.x * blockDim.x;
    int i = blockIdx.x * blockDim.x + threadIdx.x;
    for (int j = i; j < N_NODES * F1; j += stride) g_out1[j] = 0.f;
    for (int j = i; j < N_NODES * F2; j += stride) g_out2[j] = 0.f;
    for (int j = i; j < N_NODES * H1; j += stride) { g_amax1[j] = NEG_INF_KEY; g_den1[j] = 0.f; }
    for (int j = i; j < N_NODES * H2; j += stride) { g_amax2[j] = NEG_INF_KEY; g_den2[j] = 0.f; }
}

// ---------------- SGEMM: C[M,N] = A[M,K] @ B[K,N] + bias --------------------
// 64x64 block tile, 16 k-tile, 256 threads, 4x4 per-thread microtile.
__global__ void sgemm_bias(const float* __restrict__ A, const float* __restrict__ B,
                           const float* __restrict__ bias, float* __restrict__ C,
                           int M, int Nn, int K) {
    __shared__ float As[16][64];
    __shared__ float Bs[16][68];

    int tid = threadIdx.x;
    int tx = tid & 15, ty = tid >> 4;
    int rowBase = blockIdx.y * 64;
    int colBase = blockIdx.x * 64;

    int aRow = tid >> 2;        // 0..63
    int aCol = (tid & 3) * 4;   // 0,4,8,12
    int bRow = tid >> 4;        // 0..15
    int bCol = (tid & 15) * 4;  // 0..60

    float acc[4][4];
#pragma unroll
    for (int i = 0; i < 4; i++)
#pragma unroll
        for (int j = 0; j < 4; j++) acc[i][j] = 0.f;

    for (int k0 = 0; k0 < K; k0 += 16) {
        float4 av = make_float4(0.f, 0.f, 0.f, 0.f);
        if (rowBase + aRow < M)
            av = *reinterpret_cast<const float4*>(&A[(size_t)(rowBase + aRow) * K + k0 + aCol]);
        As[aCol + 0][aRow] = av.x;
        As[aCol + 1][aRow] = av.y;
        As[aCol + 2][aRow] = av.z;
        As[aCol + 3][aRow] = av.w;

        float4 bv = *reinterpret_cast<const float4*>(&B[(size_t)(k0 + bRow) * Nn + colBase + bCol]);
        Bs[bRow][bCol + 0] = bv.x;
        Bs[bRow][bCol + 1] = bv.y;
        Bs[bRow][bCol + 2] = bv.z;
        Bs[bRow][bCol + 3] = bv.w;
        __syncthreads();

#pragma unroll
        for (int kk = 0; kk < 16; kk++) {
            float a[4], b[4];
#pragma unroll
            for (int i = 0; i < 4; i++) a[i] = As[kk][ty * 4 + i];
#pragma unroll
            for (int j = 0; j < 4; j++) b[j] = Bs[kk][tx * 4 + j];
#pragma unroll
            for (int i = 0; i < 4; i++)
#pragma unroll
                for (int j = 0; j < 4; j++) acc[i][j] += a[i] * b[j];
        }
        __syncthreads();
    }

#pragma unroll
    for (int i = 0; i < 4; i++) {
        int r = rowBase + ty * 4 + i;
        if (r < M) {
#pragma unroll
            for (int j = 0; j < 4; j++) {
                int c = colBase + tx * 4 + j;
                C[(size_t)r * Nn + c] = acc[i][j] + bias[c];
            }
        }
    }
}

// ---------------- edge pass 1: alpha = <q[dst], k[src]> / sqrt(C), seg-max --
template <int H, int C>
__global__ void edge_alpha(const int* __restrict__ src, const int* __restrict__ dst,
                           const float* __restrict__ q, const float* __restrict__ k,
                           float* __restrict__ alpha, unsigned* __restrict__ amax) {
    int e = (blockIdx.x * blockDim.x + threadIdx.x) >> 5;
    if (e >= N_EDGES) return;
    int lane = threadIdx.x & 31;
    const int F = H * C;
    const int PER = F / 32;
    const int GL = 32 / H;   // lanes per head

    int s = src[e], d = dst[e];
    const float* qr = q + (size_t)d * F + lane * PER;
    const float* kr = k + (size_t)s * F + lane * PER;
    float sum = 0.f;
#pragma unroll
    for (int i = 0; i < PER; i++) sum += qr[i] * kr[i];
#pragma unroll
    for (int o = GL / 2; o > 0; o >>= 1) sum += __shfl_xor_sync(0xFFFFFFFFu, sum, o);

    if ((lane % GL) == 0) {
        int h = lane / GL;
        float a = sum * 0.125f;   // 1/sqrt(64)
        alpha[(size_t)e * H + h] = a;
        atomicMax(&amax[(size_t)d * H + h], fkey(a));
    }
}

// ---------------- edge pass 2: ex = exp(alpha - max[dst]); seg-sum ----------
template <int H>
__global__ void edge_exp(const int* __restrict__ dst, float* __restrict__ alpha,
                         const unsigned* __restrict__ amax, float* __restrict__ den) {
    int i = blockIdx.x * blockDim.x + threadIdx.x;
    if (i >= N_EDGES * H) return;
    int e = i / H, h = i - e * H;
    int d = dst[e];
    float m = funkey(amax[(size_t)d * H + h]);
    float ex = expf(alpha[i] - m);
    alpha[i] = ex;
    atomicAdd(&den[(size_t)d * H + h], ex);
}

// ---------------- edge pass 3: out[dst] += v[src] * attn --------------------
template <int H, int C>
__global__ void edge_agg(const int* __restrict__ src, const int* __restrict__ dst,
                         const float* __restrict__ v, const float* __restrict__ ex,
                         const float* __restrict__ den, float* __restrict__ out) {
    int e = (blockIdx.x * blockDim.x + threadIdx.x) >> 5;
    if (e >= N_EDGES) return;
    int lane = threadIdx.x & 31;
    const int F = H * C;
    const int PER = F / 32;
    const int GL = 32 / H;

    int s = src[e], d = dst[e];
    int h = lane / GL;
    float attn = ex[(size_t)e * H + h] / (den[(size_t)d * H + h] + 1e-16f);
    const float* vr = v + (size_t)s * F + lane * PER;
    float* orow = out + (size_t)d * F + lane * PER;
#pragma unroll
    for (int i = 0; i < PER; i++) atomicAdd(&orow[i], vr[i] * attn);
}

// ---------------- gated beta skip: y = beta*r + (1-beta)*out  (opt ReLU) ----
template <int F, bool RELU>
__global__ void beta_kernel(const float* __restrict__ out, const float* __restrict__ r,
                            const float* __restrict__ wb, float* __restrict__ y) {
    int node = (blockIdx.x * blockDim.x + threadIdx.x) >> 5;
    if (node >= N_NODES) return;
    int lane = threadIdx.x & 31;
    const int PER = F / 32;

    float o[PER], rr[PER];
    float s = 0.f;
#pragma unroll
    for (int i = 0; i < PER; i++) {
        int c = lane * PER + i;
        o[i] = out[(size_t)node * F + c];
        rr[i] = r[(size_t)node * F + c];
        s += o[i] * wb[c] + rr[i] * wb[F + c] + (o[i] - rr[i]) * wb[2 * F + c];
    }
#pragma unroll
    for (int off = 16; off > 0; off >>= 1) s += __shfl_xor_sync(0xFFFFFFFFu, s, off);
    float beta = 1.f / (1.f + expf(-s));
#pragma unroll
    for (int i = 0; i < PER; i++) {
        float val = beta * rr[i] + (1.f - beta) * o[i];
        if (RELU) val = fmaxf(val, 0.f);
        y[(size_t)node * F + lane * PER + i] = val;
    }
}

// ---------------- final: log_softmax(out) | out ------------------------------
__global__ void lsm_kernel(const float* __restrict__ y, float* __restrict__ ob, int dup) {
    int node = (blockIdx.x * blockDim.x + threadIdx.x) >> 5;
    if (node >= N_NODES) return;
    int lane = threadIdx.x & 31;
    float v0 = y[(size_t)node * 64 + lane];
    float v1 = y[(size_t)node * 64 + 32 + lane];
    float m = fmaxf(v0, v1);
#pragma unroll
    for (int o = 16; o > 0; o >>= 1) m = fmaxf(m, __shfl_xor_sync(0xFFFFFFFFu, m, o));
    float s = expf(v0 - m) + expf(v1 - m);
#pragma unroll
    for (int o = 16; o > 0; o >>= 1) s += __shfl_xor_sync(0xFFFFFFFFu, s, o);
    float ls = m + logf(s);
    ob[(size_t)node * 64 + lane] = v0 - ls;
    ob[(size_t)node * 64 + 32 + lane] = v1 - ls;
    if (dup) {
        size_t off = (size_t)N_NODES * 64;
        ob[off + (size_t)node * 64 + lane] = v0;
        ob[off + (size_t)node * 64 + 32 + lane] = v1;
    }
}

// ---------------- host launcher ---------------------------------------------
extern "C" void kernel_launch(void* const* d_in, const int* in_sizes, int n_in,
                              void* d_out, int out_size) {
    const float* x   = (const float*)d_in[0];
    const int*   ei  = (const int*)d_in[1];
    const int*   src = ei;
    const int*   dst = ei + N_EDGES;

    const float* wq1 = (const float*)d_in[3];
    const float* bq1 = (const float*)d_in[4];
    const float* wk1 = (const float*)d_in[5];
    const float* bk1 = (const float*)d_in[6];
    const float* wv1 = (const float*)d_in[7];
    const float* bv1 = (const float*)d_in[8];
    const float* ws1 = (const float*)d_in[9];
    const float* bs1 = (const float*)d_in[10];
    const float* wb1 = (const float*)d_in[11];
    const float* wq2 = (const float*)d_in[12];
    const float* bq2 = (const float*)d_in[13];
    const float* wk2 = (const float*)d_in[14];
    const float* bk2 = (const float*)d_in[15];
    const float* wv2 = (const float*)d_in[16];
    const float* bv2 = (const float*)d_in[17];
    const float* ws2 = (const float*)d_in[18];
    const float* bs2 = (const float*)d_in[19];
    const float* wb2 = (const float*)d_in[20];

    float *q1, *k1, *v1, *r1, *out1, *h, *alpha1, *den1;
    float *q2, *k2, *v2, *r2, *out2, *y2, *alpha2, *den2;
    unsigned *amax1, *amax2;
    cudaGetSymbolAddress((void**)&q1, g_q1);
    cudaGetSymbolAddress((void**)&k1, g_k1);
    cudaGetSymbolAddress((void**)&v1, g_v1);
    cudaGetSymbolAddress((void**)&r1, g_r1);
    cudaGetSymbolAddress((void**)&out1, g_out1);
    cudaGetSymbolAddress((void**)&h, g_h);
    cudaGetSymbolAddress((void**)&alpha1, g_alpha1);
    cudaGetSymbolAddress((void**)&amax1, g_amax1);
    cudaGetSymbolAddress((void**)&den1, g_den1);
    cudaGetSymbolAddress((void**)&q2, g_q2);
    cudaGetSymbolAddress((void**)&k2, g_k2);
    cudaGetSymbolAddress((void**)&v2, g_v2);
    cudaGetSymbolAddress((void**)&r2, g_r2);
    cudaGetSymbolAddress((void**)&out2, g_out2);
    cudaGetSymbolAddress((void**)&y2, g_y2);
    cudaGetSymbolAddress((void**)&alpha2, g_alpha2);
    cudaGetSymbolAddress((void**)&amax2, g_amax2);
    cudaGetSymbolAddress((void**)&den2, g_den2);

    init_kernel<<<512, 256>>>();

    // ---- layer 1 linear projections: x[N,128] @ W[128,256] + b ----
    dim3 g1(F1 / 64, (N_NODES + 63) / 64);
    sgemm_bias<<<g1, 256>>>(x, wq1, bq1, q1, N_NODES, F1, IN_CH);
    sgemm_bias<<<g1, 256>>>(x, wk1, bk1, k1, N_NODES, F1, IN_CH);
    sgemm_bias<<<g1, 256>>>(x, wv1, bv1, v1, N_NODES, F1, IN_CH);
    sgemm_bias<<<g1, 256>>>(x, ws1, bs1, r1, N_NODES, F1, IN_CH);

    // ---- layer 1 attention ----
    int eb = (N_EDGES + 7) / 8;  // warp per edge, 8 warps/block
    edge_alpha<H1, 64><<<eb, 256>>>(src, dst, q1, k1, alpha1, amax1);
    edge_exp<H1><<<(N_EDGES * H1 + 255) / 256, 256>>>(dst, alpha1, amax1, den1);
    edge_agg<H1, 64><<<eb, 256>>>(src, dst, v1, alpha1, den1, out1);

    int nb = (N_NODES + 7) / 8;
    beta_kernel<F1, true><<<nb, 256>>>(out1, r1, wb1, h);

    // ---- layer 2 linear projections: h[N,256] @ W[256,64] + b ----
    dim3 g2(F2 / 64, (N_NODES + 63) / 64);
    sgemm_bias<<<g2, 256>>>(h, wq2, bq2, q2, N_NODES, F2, F1);
    sgemm_bias<<<g2, 256>>>(h, wk2, bk2, k2, N_NODES, F2, F1);
    sgemm_bias<<<g2, 256>>>(h, wv2, bv2, v2, N_NODES, F2, F1);
    sgemm_bias<<<g2, 256>>>(h, ws2, bs2, r2, N_NODES, F2, F1);

    // ---- layer 2 attention ----
    edge_alpha<H2, 64><<<eb, 256>>>(src, dst, q2, k2, alpha2, amax2);
    edge_exp<H2><<<(N_EDGES * H2 + 255) / 256, 256>>>(dst, alpha2, amax2, den2);
    edge_agg<H2, 64><<<eb, 256>>>(src, dst, v2, alpha2, den2, out2);

    beta_kernel<F2, false><<<nb, 256>>>(out2, r2, wb2, y2);

    // ---- log_softmax + duplicate raw output ----
    int dup = (out_size >= 2 * N_NODES * F2) ? 1 : 0;
    lsm_kernel<<<nb, 256>>>(y2, (float*)d_out, dup);
}

// round 2
// speedup vs baseline: 2.1113x; 2.1113x over previous
#include <cuda_runtime.h>
#include <math.h>
#include <stdint.h>

#define N_NODES 50000
#define N_EDGES 800000
#define IN_CH   128
#define F1      256   // heads*out layer1
#define F2      64
#define H1      4
#define H2      1

// ---------------- scratch (device globals; no allocation allowed) -----------
__device__ float g_q1[N_NODES * F1];
__device__ float g_k1[N_NODES * F1];
__device__ float g_v1[N_NODES * F1];
__device__ float g_r1[N_NODES * F1];
__device__ float g_out1[N_NODES * F1];
__device__ float g_h[N_NODES * F1];

__device__ float g_q2[N_NODES * F2];
__device__ float g_k2[N_NODES * F2];
__device__ float g_v2[N_NODES * F2];
__device__ float g_r2[N_NODES * F2];
__device__ float g_out2[N_NODES * F2];
__device__ float g_y2[N_NODES * F2];

// CSR scratch
__device__ int g_deg[N_NODES];
__device__ int g_off[N_NODES + 1];
__device__ int g_pos[N_NODES];
__device__ int g_csr_src[N_EDGES];

// ---------------- CSR build --------------------------------------------------
__global__ void deg_zero_kernel() {
    int i = blockIdx.x * blockDim.x + threadIdx.x;
    if (i < N_NODES) g_deg[i] = 0;
}

__global__ void deg_count_kernel(const int* __restrict__ dst) {
    int e = blockIdx.x * blockDim.x + threadIdx.x;
    if (e < N_EDGES) atomicAdd(&g_deg[dst[e]], 1);
}

// single-block exclusive scan over degrees -> offsets (+ pos copy)
__global__ void scan_kernel() {
    __shared__ int part[1024];
    const int CH = (N_NODES + 1023) / 1024;
    int t = threadIdx.x;
    int base = t * CH;
    int sum = 0;
    for (int i = 0; i < CH; i++) {
        int idx = base + i;
        if (idx < N_NODES) sum += g_deg[idx];
    }
    part[t] = sum;
    __syncthreads();
    // Hillis-Steele inclusive scan
    for (int off = 1; off < 1024; off <<= 1) {
        int v = (t >= off) ? part[t - off] : 0;
        __syncthreads();
        part[t] += v;
        __syncthreads();
    }
    int run = (t == 0) ? 0 : part[t - 1];
    for (int i = 0; i < CH; i++) {
        int idx = base + i;
        if (idx < N_NODES) {
            g_off[idx] = run;
            g_pos[idx] = run;
            run += g_deg[idx];
        }
    }
    if (t == 1023) g_off[N_NODES] = run;
}

__global__ void scatter_kernel(const int* __restrict__ src, const int* __restrict__ dst) {
    int e = blockIdx.x * blockDim.x + threadIdx.x;
    if (e < N_EDGES) {
        int slot = atomicAdd(&g_pos[dst[e]], 1);
        g_csr_src[slot] = src[e];
    }
}

// ---------------- SGEMM: C[M,N] = A[M,K] @ B[K,N] + bias --------------------
// 128x64 block tile, k-tile 16, 256 threads, 8x4 per-thread microtile.
__global__ __launch_bounds__(256) void sgemm_bias(
        const float* __restrict__ A, const float* __restrict__ B,
        const float* __restrict__ bias, float* __restrict__ C,
        int M, int Nn, int K) {
    __shared__ float As[16][128];
    __shared__ float Bs[16][64];

    int tid = threadIdx.x;
    int tx = tid & 15;        // 0..15, N groups of 4
    int ty = tid >> 4;        // 0..15, M groups of 8
    int rowBase = blockIdx.y * 128;
    int colBase = blockIdx.x * 64;

    // A loads: 128x16 = 2048 floats, each thread 2 x float4
    int aRow = tid >> 2;            // 0..63 (and +64)
    int aCol = (tid & 3) * 4;       // 0,4,8,12
    // B loads: 16x64 = 1024 floats, each thread 1 x float4
    int bRow = tid >> 4;            // 0..15
    int bCol = (tid & 15) * 4;      // 0..60

    float acc[8][4];
#pragma unroll
    for (int i = 0; i < 8; i++)
#pragma unroll
        for (int j = 0; j < 4; j++) acc[i][j] = 0.f;

    for (int k0 = 0; k0 < K; k0 += 16) {
#pragma unroll
        for (int half = 0; half < 2; half++) {
            int r = aRow + half * 64;
            float4 av = make_float4(0.f, 0.f, 0.f, 0.f);
            if (rowBase + r < M)
                av = *reinterpret_cast<const float4*>(&A[(size_t)(rowBase + r) * K + k0 + aCol]);
            As[aCol + 0][r] = av.x;
            As[aCol + 1][r] = av.y;
            As[aCol + 2][r] = av.z;
            As[aCol + 3][r] = av.w;
        }
        float4 bv = *reinterpret_cast<const float4*>(&B[(size_t)(k0 + bRow) * Nn + colBase + bCol]);
        *reinterpret_cast<float4*>(&Bs[bRow][bCol]) = bv;
        __syncthreads();

#pragma unroll
        for (int kk = 0; kk < 16; kk++) {
            float4 a0 = *reinterpret_cast<const float4*>(&As[kk][ty * 8]);
            float4 a1 = *reinterpret_cast<const float4*>(&As[kk][ty * 8 + 4]);
            float4 b0 = *reinterpret_cast<const float4*>(&Bs[kk][tx * 4]);
            float a[8] = {a0.x, a0.y, a0.z, a0.w, a1.x, a1.y, a1.z, a1.w};
            float b[4] = {b0.x, b0.y, b0.z, b0.w};
#pragma unroll
            for (int i = 0; i < 8; i++)
#pragma unroll
                for (int j = 0; j < 4; j++) acc[i][j] += a[i] * b[j];
        }
        __syncthreads();
    }

#pragma unroll
    for (int i = 0; i < 8; i++) {
        int r = rowBase + ty * 8 + i;
        if (r < M) {
#pragma unroll
            for (int j = 0; j < 4; j++) {
                int c = colBase + tx * 4 + j;
                C[(size_t)r * Nn + c] = acc[i][j] + bias[c];
            }
        }
    }
}

// ---------------- fused attention: warp per (node, head) --------------------
// Pass A over in-edges: alpha max.  Pass B: exp/sum + weighted V accumulate.
// No atomics, no scratch, single coalesced output write.
template <int H>
__global__ __launch_bounds__(256) void node_attn(
        const float* __restrict__ q, const float* __restrict__ k,
        const float* __restrict__ v, float* __restrict__ out) {
    int wid = (blockIdx.x * blockDim.x + threadIdx.x) >> 5;
    if (wid >= N_NODES * H) return;
    int lane = threadIdx.x & 31;
    int n = wid / H, h = wid - n * H;
    const int F = H * 64;
    size_t rowcol = (size_t)n * F + h * 64 + lane * 2;

    float2 qv = *reinterpret_cast<const float2*>(&q[rowcol]);
    int beg = g_off[n], end = g_off[n + 1];

    // pass A: max of scaled dot
    float m = -3.4e38f;
    for (int i = beg; i < end; i++) {
        int s = g_csr_src[i];
        float2 kv = *reinterpret_cast<const float2*>(&k[(size_t)s * F + h * 64 + lane * 2]);
        float d = qv.x * kv.x + qv.y * kv.y;
#pragma unroll
        for (int o = 16; o > 0; o >>= 1) d += __shfl_xor_sync(0xFFFFFFFFu, d, o);
        m = fmaxf(m, d);
    }
    m *= 0.125f;  // 1/sqrt(64); positive scale commutes with max

    // pass B: recompute dot (bit-identical), exp, sum, accumulate v
    float ssum = 0.f;
    float accx = 0.f, accy = 0.f;
    for (int i = beg; i < end; i++) {
        int s = g_csr_src[i];
        size_t sc = (size_t)s * F + h * 64 + lane * 2;
        float2 kv = *reinterpret_cast<const float2*>(&k[sc]);
        float2 vv = *reinterpret_cast<const float2*>(&v[sc]);
        float d = qv.x * kv.x + qv.y * kv.y;
#pragma unroll
        for (int o = 16; o > 0; o >>= 1) d += __shfl_xor_sync(0xFFFFFFFFu, d, o);
        float p = expf(d * 0.125f - m);
        ssum += p;
        accx += p * vv.x;
        accy += p * vv.y;
    }
    float inv = 1.f / (ssum + 1e-16f);
    float2 res = make_float2(accx * inv, accy * inv);
    *reinterpret_cast<float2*>(&out[rowcol]) = res;
}

// ---------------- gated beta skip: y = beta*r + (1-beta)*out  (opt ReLU) ----
template <int F, bool RELU>
__global__ void beta_kernel(const float* __restrict__ out, const float* __restrict__ r,
                            const float* __restrict__ wb, float* __restrict__ y) {
    int node = (blockIdx.x * blockDim.x + threadIdx.x) >> 5;
    if (node >= N_NODES) return;
    int lane = threadIdx.x & 31;
    const int PER = F / 32;

    float o[PER], rr[PER];
    float s = 0.f;
#pragma unroll
    for (int i = 0; i < PER; i++) {
        int c = lane * PER + i;
        o[i] = out[(size_t)node * F + c];
        rr[i] = r[(size_t)node * F + c];
        s += o[i] * wb[c] + rr[i] * wb[F + c] + (o[i] - rr[i]) * wb[2 * F + c];
    }
#pragma unroll
    for (int off = 16; off > 0; off >>= 1) s += __shfl_xor_sync(0xFFFFFFFFu, s, off);
    float beta = 1.f / (1.f + expf(-s));
#pragma unroll
    for (int i = 0; i < PER; i++) {
        float val = beta * rr[i] + (1.f - beta) * o[i];
        if (RELU) val = fmaxf(val, 0.f);
        y[(size_t)node * F + lane * PER + i] = val;
    }
}

// ---------------- final: log_softmax(out) | out ------------------------------
__global__ void lsm_kernel(const float* __restrict__ y, float* __restrict__ ob, int dup) {
    int node = (blockIdx.x * blockDim.x + threadIdx.x) >> 5;
    if (node >= N_NODES) return;
    int lane = threadIdx.x & 31;
    float v0 = y[(size_t)node * 64 + lane];
    float v1 = y[(size_t)node * 64 + 32 + lane];
    float m = fmaxf(v0, v1);
#pragma unroll
    for (int o = 16; o > 0; o >>= 1) m = fmaxf(m, __shfl_xor_sync(0xFFFFFFFFu, m, o));
    float s = expf(v0 - m) + expf(v1 - m);
#pragma unroll
    for (int o = 16; o > 0; o >>= 1) s += __shfl_xor_sync(0xFFFFFFFFu, s, o);
    float ls = m + logf(s);
    ob[(size_t)node * 64 + lane] = v0 - ls;
    ob[(size_t)node * 64 + 32 + lane] = v1 - ls;
    if (dup) {
        size_t off = (size_t)N_NODES * 64;
        ob[off + (size_t)node * 64 + lane] = v0;
        ob[off + (size_t)node * 64 + 32 + lane] = v1;
    }
}

// ---------------- host launcher ---------------------------------------------
extern "C" void kernel_launch(void* const* d_in, const int* in_sizes, int n_in,
                              void* d_out, int out_size) {
    const float* x   = (const float*)d_in[0];
    const int*   ei  = (const int*)d_in[1];
    const int*   src = ei;
    const int*   dst = ei + N_EDGES;

    const float* wq1 = (const float*)d_in[3];
    const float* bq1 = (const float*)d_in[4];
    const float* wk1 = (const float*)d_in[5];
    const float* bk1 = (const float*)d_in[6];
    const float* wv1 = (const float*)d_in[7];
    const float* bv1 = (const float*)d_in[8];
    const float* ws1 = (const float*)d_in[9];
    const float* bs1 = (const float*)d_in[10];
    const float* wb1 = (const float*)d_in[11];
    const float* wq2 = (const float*)d_in[12];
    const float* bq2 = (const float*)d_in[13];
    const float* wk2 = (const float*)d_in[14];
    const float* bk2 = (const float*)d_in[15];
    const float* wv2 = (const float*)d_in[16];
    const float* bv2 = (const float*)d_in[17];
    const float* ws2 = (const float*)d_in[18];
    const float* bs2 = (const float*)d_in[19];
    const float* wb2 = (const float*)d_in[20];

    float *q1, *k1, *v1, *r1, *out1, *h;
    float *q2, *k2, *v2, *r2, *out2, *y2;
    cudaGetSymbolAddress((void**)&q1, g_q1);
    cudaGetSymbolAddress((void**)&k1, g_k1);
    cudaGetSymbolAddress((void**)&v1, g_v1);
    cudaGetSymbolAddress((void**)&r1, g_r1);
    cudaGetSymbolAddress((void**)&out1, g_out1);
    cudaGetSymbolAddress((void**)&h, g_h);
    cudaGetSymbolAddress((void**)&q2, g_q2);
    cudaGetSymbolAddress((void**)&k2, g_k2);
    cudaGetSymbolAddress((void**)&v2, g_v2);
    cudaGetSymbolAddress((void**)&r2, g_r2);
    cudaGetSymbolAddress((void**)&out2, g_out2);
    cudaGetSymbolAddress((void**)&y2, g_y2);

    // ---- CSR build (shared by both layers) ----
    deg_zero_kernel<<<(N_NODES + 255) / 256, 256>>>();
    deg_count_kernel<<<(N_EDGES + 255) / 256, 256>>>(dst);
    scan_kernel<<<1, 1024>>>();
    scatter_kernel<<<(N_EDGES + 255) / 256, 256>>>(src, dst);

    // ---- layer 1 linear projections: x[N,128] @ W[128,256] + b ----
    dim3 g1(F1 / 64, (N_NODES + 127) / 128);
    sgemm_bias<<<g1, 256>>>(x, wq1, bq1, q1, N_NODES, F1, IN_CH);
    sgemm_bias<<<g1, 256>>>(x, wk1, bk1, k1, N_NODES, F1, IN_CH);
    sgemm_bias<<<g1, 256>>>(x, wv1, bv1, v1, N_NODES, F1, IN_CH);
    sgemm_bias<<<g1, 256>>>(x, ws1, bs1, r1, N_NODES, F1, IN_CH);

    // ---- layer 1 fused attention (warp per node-head) ----
    int ab1 = (N_NODES * H1 + 7) / 8;  // 8 warps per block
    node_attn<H1><<<ab1, 256>>>(q1, k1, v1, out1);

    int nb = (N_NODES + 7) / 8;
    beta_kernel<F1, true><<<nb, 256>>>(out1, r1, wb1, h);

    // ---- layer 2 linear projections: h[N,256] @ W[256,64] + b ----
    dim3 g2(F2 / 64, (N_NODES + 127) / 128);
    sgemm_bias<<<g2, 256>>>(h, wq2, bq2, q2, N_NODES, F2, F1);
    sgemm_bias<<<g2, 256>>>(h, wk2, bk2, k2, N_NODES, F2, F1);
    sgemm_bias<<<g2, 256>>>(h, wv2, bv2, v2, N_NODES, F2, F1);
    sgemm_bias<<<g2, 256>>>(h, ws2, bs2, r2, N_NODES, F2, F1);

    // ---- layer 2 fused attention ----
    int ab2 = (N_NODES * H2 + 7) / 8;
    node_attn<H2><<<ab2, 256>>>(q2, k2, v2, out2);

    beta_kernel<F2, false><<<nb, 256>>>(out2, r2, wb2, y2);

    // ---- log_softmax + duplicate raw output ----
    int dup = (out_size >= 2 * N_NODES * F2) ? 1 : 0;
    lsm_kernel<<<nb, 256>>>(y2, (float*)d_out, dup);
}

// round 3
// speedup vs baseline: 3.1006x; 1.4686x over previous
#include <cuda_runtime.h>
#include <mma.h>
#include <math.h>
#include <stdint.h>

using namespace nvcuda;

#define N_NODES 50000
#define N_EDGES 800000
#define IN_CH   128
#define F1      256   // heads*out layer1
#define F2      64
#define H1      4
#define H2      1

// ---------------- scratch (device globals; no allocation allowed) -----------
__device__ float g_q1[N_NODES * F1];
__device__ float g_k1[N_NODES * F1];
__device__ float g_v1[N_NODES * F1];
__device__ float g_r1[N_NODES * F1];
__device__ float g_out1[N_NODES * F1];
__device__ float g_h[N_NODES * F1];

__device__ float g_q2[N_NODES * F2];
__device__ float g_k2[N_NODES * F2];
__device__ float g_v2[N_NODES * F2];
__device__ float g_r2[N_NODES * F2];
__device__ float g_out2[N_NODES * F2];

// CSR scratch
__device__ int g_deg[N_NODES];
__device__ int g_off[N_NODES + 1];
__device__ int g_pos[N_NODES];
__device__ int g_csr_src[N_EDGES];

// ---------------- CSR build --------------------------------------------------
__global__ void deg_zero_kernel() {
    int i = blockIdx.x * blockDim.x + threadIdx.x;
    if (i < N_NODES) g_deg[i] = 0;
}

__global__ void deg_count_kernel(const int* __restrict__ dst) {
    int e = blockIdx.x * blockDim.x + threadIdx.x;
    if (e < N_EDGES) atomicAdd(&g_deg[dst[e]], 1);
}

// single-block exclusive scan over degrees -> offsets (+ pos copy)
__global__ void scan_kernel() {
    __shared__ int part[1024];
    const int CH = (N_NODES + 1023) / 1024;
    int t = threadIdx.x;
    int base = t * CH;
    int sum = 0;
    for (int i = 0; i < CH; i++) {
        int idx = base + i;
        if (idx < N_NODES) sum += g_deg[idx];
    }
    part[t] = sum;
    __syncthreads();
    for (int off = 1; off < 1024; off <<= 1) {
        int v = (t >= off) ? part[t - off] : 0;
        __syncthreads();
        part[t] += v;
        __syncthreads();
    }
    int run = (t == 0) ? 0 : part[t - 1];
    for (int i = 0; i < CH; i++) {
        int idx = base + i;
        if (idx < N_NODES) {
            g_off[idx] = run;
            g_pos[idx] = run;
            run += g_deg[idx];
        }
    }
    if (t == 1023) g_off[N_NODES] = run;
}

__global__ void scatter_kernel(const int* __restrict__ src, const int* __restrict__ dst) {
    int e = blockIdx.x * blockDim.x + threadIdx.x;
    if (e < N_EDGES) {
        int slot = atomicAdd(&g_pos[dst[e]], 1);
        g_csr_src[slot] = src[e];
    }
}

// ---------------- TF32 GEMM: C_z = A @ B_z, 4 GEMMs share A via blockIdx.z ---
// BM=128, BN=64, BK=16. 256 threads = 8 warps, warp tile 32x32 (wmma 16x16x8).
// No bias (biases folded into consumers). M must be multiple of 16 (50000 is).
__global__ __launch_bounds__(256) void gemm4_tf32(
        const float* __restrict__ A,
        const float* __restrict__ B0, const float* __restrict__ B1,
        const float* __restrict__ B2, const float* __restrict__ B3,
        float* __restrict__ C0, float* __restrict__ C1,
        float* __restrict__ C2, float* __restrict__ C3,
        int M, int Nn, int K) {
    const float* B;
    float* C;
    switch (blockIdx.z) {
        case 0: B = B0; C = C0; break;
        case 1: B = B1; C = C1; break;
        case 2: B = B2; C = C2; break;
        default: B = B3; C = C3; break;
    }

    __shared__ float As[128][24];   // padded ldm=24
    __shared__ float Bs[16][72];    // padded ldm=72

    int tid = threadIdx.x;
    int warp = tid >> 5;
    int wm = warp & 3;   // 0..3  (m subtile of 32)
    int wn = warp >> 2;  // 0..1  (n subtile of 32)
    int rowBase = blockIdx.y * 128;
    int colBase = blockIdx.x * 64;

    int aRow = tid >> 2;        // 0..63 (+64 second half)
    int aCol = (tid & 3) * 4;   // 0,4,8,12
    int bRow = tid >> 4;        // 0..15
    int bCol = (tid & 15) * 4;  // 0..60

    wmma::fragment<wmma::accumulator, 16, 16, 8, float> acc[2][2];
#pragma unroll
    for (int i = 0; i < 2; i++)
#pragma unroll
        for (int j = 0; j < 2; j++) wmma::fill_fragment(acc[i][j], 0.0f);

    for (int k0 = 0; k0 < K; k0 += 16) {
#pragma unroll
        for (int half = 0; half < 2; half++) {
            int r = aRow + half * 64;
            float4 av = make_float4(0.f, 0.f, 0.f, 0.f);
            if (rowBase + r < M)
                av = *reinterpret_cast<const float4*>(&A[(size_t)(rowBase + r) * K + k0 + aCol]);
            As[r][aCol + 0] = av.x;
            As[r][aCol + 1] = av.y;
            As[r][aCol + 2] = av.z;
            As[r][aCol + 3] = av.w;
        }
        float4 bv = *reinterpret_cast<const float4*>(&B[(size_t)(k0 + bRow) * Nn + colBase + bCol]);
        *reinterpret_cast<float4*>(&Bs[bRow][bCol]) = bv;
        __syncthreads();

#pragma unroll
        for (int ks = 0; ks < 16; ks += 8) {
            wmma::fragment<wmma::matrix_a, 16, 16, 8, wmma::precision::tf32, wmma::row_major> af[2];
            wmma::fragment<wmma::matrix_b, 16, 16, 8, wmma::precision::tf32, wmma::row_major> bf[2];
#pragma unroll
            for (int i = 0; i < 2; i++) {
                wmma::load_matrix_sync(af[i], &As[wm * 32 + i * 16][ks], 24);
#pragma unroll
                for (int t = 0; t < af[i].num_elements; t++)
                    af[i].x[t] = wmma::__float_to_tf32(af[i].x[t]);
            }
#pragma unroll
            for (int j = 0; j < 2; j++) {
                wmma::load_matrix_sync(bf[j], &Bs[ks][wn * 32 + j * 16], 72);
#pragma unroll
                for (int t = 0; t < bf[j].num_elements; t++)
                    bf[j].x[t] = wmma::__float_to_tf32(bf[j].x[t]);
            }
#pragma unroll
            for (int i = 0; i < 2; i++)
#pragma unroll
                for (int j = 0; j < 2; j++)
                    wmma::mma_sync(acc[i][j], af[i], bf[j], acc[i][j]);
        }
        __syncthreads();
    }

#pragma unroll
    for (int i = 0; i < 2; i++) {
        int r = rowBase + wm * 32 + i * 16;
        if (r < M) {   // M % 16 == 0 -> fragment fully valid
#pragma unroll
            for (int j = 0; j < 2; j++)
                wmma::store_matrix_sync(&C[(size_t)r * Nn + colBase + wn * 32 + j * 16],
                                        acc[i][j], Nn, wmma::mem_row_major);
        }
    }
}

// ---------------- fused attention layer1: warp per node, 4 heads ------------
// Online softmax, single edge pass. Biases added in-register.
__global__ __launch_bounds__(256) void attn1_kernel(
        const float* __restrict__ q, const float* __restrict__ k,
        const float* __restrict__ v,
        const float* __restrict__ bq, const float* __restrict__ bk,
        const float* __restrict__ bv, float* __restrict__ out) {
    int n = (blockIdx.x * blockDim.x + threadIdx.x) >> 5;
    if (n >= N_NODES) return;
    int lane = threadIdx.x & 31;
    int col = lane * 8;                 // == h*64 + (lane&7)*8, h = lane>>3

    float4 q0 = *reinterpret_cast<const float4*>(&q[(size_t)n * F1 + col]);
    float4 q1 = *reinterpret_cast<const float4*>(&q[(size_t)n * F1 + col + 4]);
    float4 qb0 = *reinterpret_cast<const float4*>(&bq[col]);
    float4 qb1 = *reinterpret_cast<const float4*>(&bq[col + 4]);
    q0.x += qb0.x; q0.y += qb0.y; q0.z += qb0.z; q0.w += qb0.w;
    q1.x += qb1.x; q1.y += qb1.y; q1.z += qb1.z; q1.w += qb1.w;
    float4 kb0 = *reinterpret_cast<const float4*>(&bk[col]);
    float4 kb1 = *reinterpret_cast<const float4*>(&bk[col + 4]);
    float4 vb0 = *reinterpret_cast<const float4*>(&bv[col]);
    float4 vb1 = *reinterpret_cast<const float4*>(&bv[col + 4]);

    int beg = g_off[n], end = g_off[n + 1];
    float m = -3.4e38f, ssum = 0.f;
    float4 a0 = make_float4(0.f, 0.f, 0.f, 0.f);
    float4 a1 = make_float4(0.f, 0.f, 0.f, 0.f);

    for (int i = beg; i < end; i++) {
        int s = g_csr_src[i];
        size_t base = (size_t)s * F1 + col;
        float4 kk0 = *reinterpret_cast<const float4*>(&k[base]);
        float4 kk1 = *reinterpret_cast<const float4*>(&k[base + 4]);
        float4 vv0 = *reinterpret_cast<const float4*>(&v[base]);
        float4 vv1 = *reinterpret_cast<const float4*>(&v[base + 4]);

        float d = q0.x * (kk0.x + kb0.x) + q0.y * (kk0.y + kb0.y)
                + q0.z * (kk0.z + kb0.z) + q0.w * (kk0.w + kb0.w)
                + q1.x * (kk1.x + kb1.x) + q1.y * (kk1.y + kb1.y)
                + q1.z * (kk1.z + kb1.z) + q1.w * (kk1.w + kb1.w);
        d += __shfl_xor_sync(0xFFFFFFFFu, d, 1);
        d += __shfl_xor_sync(0xFFFFFFFFu, d, 2);
        d += __shfl_xor_sync(0xFFFFFFFFu, d, 4);   // reduce within 8-lane head group
        d *= 0.125f;                                // 1/sqrt(64)

        float mn = fmaxf(m, d);
        float sc = __expf(m - mn);
        float p = __expf(d - mn);
        ssum = ssum * sc + p;
        a0.x = a0.x * sc + p * (vv0.x + vb0.x);
        a0.y = a0.y * sc + p * (vv0.y + vb0.y);
        a0.z = a0.z * sc + p * (vv0.z + vb0.z);
        a0.w = a0.w * sc + p * (vv0.w + vb0.w);
        a1.x = a1.x * sc + p * (vv1.x + vb1.x);
        a1.y = a1.y * sc + p * (vv1.y + vb1.y);
        a1.z = a1.z * sc + p * (vv1.z + vb1.z);
        a1.w = a1.w * sc + p * (vv1.w + vb1.w);
        m = mn;
    }
    float inv = 1.f / (ssum + 1e-16f);
    a0.x *= inv; a0.y *= inv; a0.z *= inv; a0.w *= inv;
    a1.x *= inv; a1.y *= inv; a1.z *= inv; a1.w *= inv;
    *reinterpret_cast<float4*>(&out[(size_t)n * F1 + col]) = a0;
    *reinterpret_cast<float4*>(&out[(size_t)n * F1 + col + 4]) = a1;
}

// ---------------- fused attention layer2: warp per node, 1 head -------------
__global__ __launch_bounds__(256) void attn2_kernel(
        const float* __restrict__ q, const float* __restrict__ k,
        const float* __restrict__ v,
        const float* __restrict__ bq, const float* __restrict__ bk,
        const float* __restrict__ bv, float* __restrict__ out) {
    int n = (blockIdx.x * blockDim.x + threadIdx.x) >> 5;
    if (n >= N_NODES) return;
    int lane = threadIdx.x & 31;
    int col = lane * 2;

    float2 qv = *reinterpret_cast<const float2*>(&q[(size_t)n * F2 + col]);
    float2 qb = *reinterpret_cast<const float2*>(&bq[col]);
    qv.x += qb.x; qv.y += qb.y;
    float2 kb = *reinterpret_cast<const float2*>(&bk[col]);
    float2 vb = *reinterpret_cast<const float2*>(&bv[col]);

    int beg = g_off[n], end = g_off[n + 1];
    float m = -3.4e38f, ssum = 0.f;
    float ax = 0.f, ay = 0.f;

    for (int i = beg; i < end; i++) {
        int s = g_csr_src[i];
        size_t base = (size_t)s * F2 + col;
        float2 kk = *reinterpret_cast<const float2*>(&k[base]);
        float2 vv = *reinterpret_cast<const float2*>(&v[base]);
        float d = qv.x * (kk.x + kb.x) + qv.y * (kk.y + kb.y);
#pragma unroll
        for (int o = 16; o > 0; o >>= 1) d += __shfl_xor_sync(0xFFFFFFFFu, d, o);
        d *= 0.125f;

        float mn = fmaxf(m, d);
        float sc = __expf(m - mn);
        float p = __expf(d - mn);
        ssum = ssum * sc + p;
        ax = ax * sc + p * (vv.x + vb.x);
        ay = ay * sc + p * (vv.y + vb.y);
        m = mn;
    }
    float inv = 1.f / (ssum + 1e-16f);
    float2 res = make_float2(ax * inv, ay * inv);
    *reinterpret_cast<float2*>(&out[(size_t)n * F2 + col]) = res;
}

// ---------------- beta layer1: y = relu(beta*r + (1-beta)*out), r=rraw+bs ---
__global__ __launch_bounds__(256) void beta1_kernel(
        const float* __restrict__ out, const float* __restrict__ rraw,
        const float* __restrict__ bs, const float* __restrict__ wb,
        float* __restrict__ y) {
    int node = (blockIdx.x * blockDim.x + threadIdx.x) >> 5;
    if (node >= N_NODES) return;
    int lane = threadIdx.x & 31;
    int col = lane * 8;

    float o[8], rr[8];
    float s = 0.f;
#pragma unroll
    for (int u = 0; u < 2; u++) {
        float4 ov = *reinterpret_cast<const float4*>(&out[(size_t)node * F1 + col + u * 4]);
        float4 rv = *reinterpret_cast<const float4*>(&rraw[(size_t)node * F1 + col + u * 4]);
        float4 bv = *reinterpret_cast<const float4*>(&bs[col + u * 4]);
        o[u * 4 + 0] = ov.x; o[u * 4 + 1] = ov.y; o[u * 4 + 2] = ov.z; o[u * 4 + 3] = ov.w;
        rr[u * 4 + 0] = rv.x + bv.x; rr[u * 4 + 1] = rv.y + bv.y;
        rr[u * 4 + 2] = rv.z + bv.z; rr[u * 4 + 3] = rv.w + bv.w;
    }
#pragma unroll
    for (int i = 0; i < 8; i++) {
        int c = col + i;
        s += o[i] * wb[c] + rr[i] * wb[F1 + c] + (o[i] - rr[i]) * wb[2 * F1 + c];
    }
#pragma unroll
    for (int off = 16; off > 0; off >>= 1) s += __shfl_xor_sync(0xFFFFFFFFu, s, off);
    float beta = 1.f / (1.f + __expf(-s));
    float res[8];
#pragma unroll
    for (int i = 0; i < 8; i++)
        res[i] = fmaxf(beta * rr[i] + (1.f - beta) * o[i], 0.f);
    *reinterpret_cast<float4*>(&y[(size_t)node * F1 + col]) =
        make_float4(res[0], res[1], res[2], res[3]);
    *reinterpret_cast<float4*>(&y[(size_t)node * F1 + col + 4]) =
        make_float4(res[4], res[5], res[6], res[7]);
}

// ---------------- fused beta layer2 + log_softmax + dup ---------------------
__global__ __launch_bounds__(256) void beta2_lsm_kernel(
        const float* __restrict__ out, const float* __restrict__ rraw,
        const float* __restrict__ bs, const float* __restrict__ wb,
        float* __restrict__ ob, int dup) {
    int node = (blockIdx.x * blockDim.x + threadIdx.x) >> 5;
    if (node >= N_NODES) return;
    int lane = threadIdx.x & 31;
    int col = lane * 2;

    float2 ov = *reinterpret_cast<const float2*>(&out[(size_t)node * F2 + col]);
    float2 rv = *reinterpret_cast<const float2*>(&rraw[(size_t)node * F2 + col]);
    float2 bv = *reinterpret_cast<const float2*>(&bs[col]);
    float o0 = ov.x, o1 = ov.y;
    float r0 = rv.x + bv.x, r1 = rv.y + bv.y;

    float s = o0 * wb[col] + o1 * wb[col + 1]
            + r0 * wb[F2 + col] + r1 * wb[F2 + col + 1]
            + (o0 - r0) * wb[2 * F2 + col] + (o1 - r1) * wb[2 * F2 + col + 1];
#pragma unroll
    for (int off = 16; off > 0; off >>= 1) s += __shfl_xor_sync(0xFFFFFFFFu, s, off);
    float beta = 1.f / (1.f + __expf(-s));
    float v0 = beta * r0 + (1.f - beta) * o0;
    float v1 = beta * r1 + (1.f - beta) * o1;

    float m = fmaxf(v0, v1);
#pragma unroll
    for (int o = 16; o > 0; o >>= 1) m = fmaxf(m, __shfl_xor_sync(0xFFFFFFFFu, m, o));
    float es = expf(v0 - m) + expf(v1 - m);
#pragma unroll
    for (int o = 16; o > 0; o >>= 1) es += __shfl_xor_sync(0xFFFFFFFFu, es, o);
    float ls = m + logf(es);

    *reinterpret_cast<float2*>(&ob[(size_t)node * F2 + col]) =
        make_float2(v0 - ls, v1 - ls);
    if (dup) {
        size_t off = (size_t)N_NODES * F2;
        *reinterpret_cast<float2*>(&ob[off + (size_t)node * F2 + col]) =
            make_float2(v0, v1);
    }
}

// ---------------- host launcher ---------------------------------------------
extern "C" void kernel_launch(void* const* d_in, const int* in_sizes, int n_in,
                              void* d_out, int out_size) {
    const float* x   = (const float*)d_in[0];
    const int*   ei  = (const int*)d_in[1];
    const int*   src = ei;
    const int*   dst = ei + N_EDGES;

    const float* wq1 = (const float*)d_in[3];
    const float* bq1 = (const float*)d_in[4];
    const float* wk1 = (const float*)d_in[5];
    const float* bk1 = (const float*)d_in[6];
    const float* wv1 = (const float*)d_in[7];
    const float* bv1 = (const float*)d_in[8];
    const float* ws1 = (const float*)d_in[9];
    const float* bs1 = (const float*)d_in[10];
    const float* wb1 = (const float*)d_in[11];
    const float* wq2 = (const float*)d_in[12];
    const float* bq2 = (const float*)d_in[13];
    const float* wk2 = (const float*)d_in[14];
    const float* bk2 = (const float*)d_in[15];
    const float* wv2 = (const float*)d_in[16];
    const float* bv2 = (const float*)d_in[17];
    const float* ws2 = (const float*)d_in[18];
    const float* bs2 = (const float*)d_in[19];
    const float* wb2 = (const float*)d_in[20];

    float *q1, *k1, *v1, *r1, *out1, *h;
    float *q2, *k2, *v2, *r2, *out2;
    cudaGetSymbolAddress((void**)&q1, g_q1);
    cudaGetSymbolAddress((void**)&k1, g_k1);
    cudaGetSymbolAddress((void**)&v1, g_v1);
    cudaGetSymbolAddress((void**)&r1, g_r1);
    cudaGetSymbolAddress((void**)&out1, g_out1);
    cudaGetSymbolAddress((void**)&h, g_h);
    cudaGetSymbolAddress((void**)&q2, g_q2);
    cudaGetSymbolAddress((void**)&k2, g_k2);
    cudaGetSymbolAddress((void**)&v2, g_v2);
    cudaGetSymbolAddress((void**)&r2, g_r2);
    cudaGetSymbolAddress((void**)&out2, g_out2);

    // ---- CSR build ----
    deg_zero_kernel<<<(N_NODES + 255) / 256, 256>>>();
    deg_count_kernel<<<(N_EDGES + 255) / 256, 256>>>(dst);
    scan_kernel<<<1, 1024>>>();
    scatter_kernel<<<(N_EDGES + 255) / 256, 256>>>(src, dst);

    // ---- layer 1: 4 GEMMs in one launch (x shared) ----
    dim3 g1(F1 / 64, (N_NODES + 127) / 128, 4);
    gemm4_tf32<<<g1, 256>>>(x, wq1, wk1, wv1, ws1, q1, k1, v1, r1,
                            N_NODES, F1, IN_CH);

    attn1_kernel<<<(N_NODES + 7) / 8, 256>>>(q1, k1, v1, bq1, bk1, bv1, out1);
    beta1_kernel<<<(N_NODES + 7) / 8, 256>>>(out1, r1, bs1, wb1, h);

    // ---- layer 2: 4 GEMMs in one launch (h shared) ----
    dim3 g2(F2 / 64, (N_NODES + 127) / 128, 4);
    gemm4_tf32<<<g2, 256>>>(h, wq2, wk2, wv2, ws2, q2, k2, v2, r2,
                            N_NODES, F2, F1);

    attn2_kernel<<<(N_NODES + 7) / 8, 256>>>(q2, k2, v2, bq2, bk2, bv2, out2);

    int dup = (out_size >= 2 * N_NODES * F2) ? 1 : 0;
    beta2_lsm_kernel<<<(N_NODES + 7) / 8, 256>>>(out2, r2, bs2, wb2,
                                                 (float*)d_out, dup);
}

// round 4
// speedup vs baseline: 3.1489x; 1.0156x over previous
#include <cuda_runtime.h>
#include <mma.h>
#include <math.h>
#include <stdint.h>

using namespace nvcuda;

#define N_NODES 50000
#define N_EDGES 800000
#define IN_CH   128
#define F1      256   // heads*out layer1
#define F2      64
#define H1      4

// ---------------- scratch (device globals; no allocation allowed) -----------
__device__ float g_q1[N_NODES * F1];
__device__ float g_k1[N_NODES * F1];
__device__ float g_v1[N_NODES * F1];
__device__ float g_r1[N_NODES * F1];
__device__ float g_h[N_NODES * F1];

__device__ float g_q2[N_NODES * F2];
__device__ float g_k2[N_NODES * F2];
__device__ float g_v2[N_NODES * F2];
__device__ float g_r2[N_NODES * F2];

// CSR scratch
__device__ int g_deg[N_NODES];
__device__ int g_off[N_NODES + 1];
__device__ int g_pos[N_NODES];
__device__ int g_csr_src[N_EDGES];

// ---------------- cp.async helpers ------------------------------------------
__device__ __forceinline__ void cp_async16(uint32_t saddr, const void* gptr) {
    asm volatile("cp.async.cg.shared.global [%0], [%1], 16;\n"
                 :: "r"(saddr), "l"(gptr));
}
__device__ __forceinline__ void cp_commit() {
    asm volatile("cp.async.commit_group;\n");
}
template <int N>
__device__ __forceinline__ void cp_wait() {
    asm volatile("cp.async.wait_group %0;\n" :: "n"(N));
}

// ---------------- CSR build --------------------------------------------------
__global__ void deg_zero_kernel() {
    int i = blockIdx.x * blockDim.x + threadIdx.x;
    if (i < N_NODES) g_deg[i] = 0;
}

__global__ void deg_count_kernel(const int* __restrict__ dst) {
    int e = blockIdx.x * blockDim.x + threadIdx.x;
    if (e < N_EDGES) atomicAdd(&g_deg[dst[e]], 1);
}

__global__ void scan_kernel() {
    __shared__ int part[1024];
    const int CH = (N_NODES + 1023) / 1024;
    int t = threadIdx.x;
    int base = t * CH;
    int sum = 0;
    for (int i = 0; i < CH; i++) {
        int idx = base + i;
        if (idx < N_NODES) sum += g_deg[idx];
    }
    part[t] = sum;
    __syncthreads();
    for (int off = 1; off < 1024; off <<= 1) {
        int v = (t >= off) ? part[t - off] : 0;
        __syncthreads();
        part[t] += v;
        __syncthreads();
    }
    int run = (t == 0) ? 0 : part[t - 1];
    for (int i = 0; i < CH; i++) {
        int idx = base + i;
        if (idx < N_NODES) {
            g_off[idx] = run;
            g_pos[idx] = run;
            run += g_deg[idx];
        }
    }
    if (t == 1023) g_off[N_NODES] = run;
}

__global__ void scatter_kernel(const int* __restrict__ src, const int* __restrict__ dst) {
    int e = blockIdx.x * blockDim.x + threadIdx.x;
    if (e < N_EDGES) {
        int slot = atomicAdd(&g_pos[dst[e]], 1);
        g_csr_src[slot] = src[e];
    }
}

// ---------------- TF32 GEMM, cp.async double-buffered ------------------------
// C_z = A @ B_z (4 GEMMs share A via blockIdx.z). BM=128, BN=64, BK=16.
// 256 threads = 8 warps, warp tile 32x32 (wmma 16x16x8). No bias.
__global__ __launch_bounds__(256) void gemm4_tf32(
        const float* __restrict__ A,
        const float* __restrict__ B0, const float* __restrict__ B1,
        const float* __restrict__ B2, const float* __restrict__ B3,
        float* __restrict__ C0, float* __restrict__ C1,
        float* __restrict__ C2, float* __restrict__ C3,
        int M, int Nn, int K) {
    const float* B;
    float* C;
    switch (blockIdx.z) {
        case 0: B = B0; C = C0; break;
        case 1: B = B1; C = C1; break;
        case 2: B = B2; C = C2; break;
        default: B = B3; C = C3; break;
    }

    __shared__ float As[2][128][24];   // padded ldm=24
    __shared__ float Bs[2][16][72];    // padded ldm=72

    int tid = threadIdx.x;
    int warp = tid >> 5;
    int wm = warp & 3;
    int wn = warp >> 2;
    int rowBase = blockIdx.y * 128;
    int colBase = blockIdx.x * 64;

    int aRow = tid >> 2;        // 0..63 (+64 second half)
    int aCol = (tid & 3) * 4;   // 0,4,8,12
    int bRow = tid >> 4;        // 0..15
    int bCol = (tid & 15) * 4;  // 0..60

    // global row clamped (last block partial; clamped rows never stored)
    int gr0 = rowBase + aRow;       if (gr0 >= M) gr0 = M - 1;
    int gr1 = rowBase + aRow + 64;  if (gr1 >= M) gr1 = M - 1;

    uint32_t sA0[2], sA1[2], sB[2];
#pragma unroll
    for (int st = 0; st < 2; st++) {
        sA0[st] = (uint32_t)__cvta_generic_to_shared(&As[st][aRow][aCol]);
        sA1[st] = (uint32_t)__cvta_generic_to_shared(&As[st][aRow + 64][aCol]);
        sB[st]  = (uint32_t)__cvta_generic_to_shared(&Bs[st][bRow][bCol]);
    }

    wmma::fragment<wmma::accumulator, 16, 16, 8, float> acc[2][2];
#pragma unroll
    for (int i = 0; i < 2; i++)
#pragma unroll
        for (int j = 0; j < 2; j++) wmma::fill_fragment(acc[i][j], 0.0f);

    // prologue: stage 0
    cp_async16(sA0[0], &A[(size_t)gr0 * K + aCol]);
    cp_async16(sA1[0], &A[(size_t)gr1 * K + aCol]);
    cp_async16(sB[0],  &B[(size_t)bRow * Nn + colBase + bCol]);
    cp_commit();

    int st = 0;
    for (int k0 = 0; k0 < K; k0 += 16) {
        if (k0 + 16 < K) {
            int ns = st ^ 1;
            cp_async16(sA0[ns], &A[(size_t)gr0 * K + k0 + 16 + aCol]);
            cp_async16(sA1[ns], &A[(size_t)gr1 * K + k0 + 16 + aCol]);
            cp_async16(sB[ns],  &B[(size_t)(k0 + 16 + bRow) * Nn + colBase + bCol]);
        }
        cp_commit();
        cp_wait<1>();
        __syncthreads();

#pragma unroll
        for (int ks = 0; ks < 16; ks += 8) {
            wmma::fragment<wmma::matrix_a, 16, 16, 8, wmma::precision::tf32, wmma::row_major> af[2];
            wmma::fragment<wmma::matrix_b, 16, 16, 8, wmma::precision::tf32, wmma::row_major> bf[2];
#pragma unroll
            for (int i = 0; i < 2; i++) {
                wmma::load_matrix_sync(af[i], &As[st][wm * 32 + i * 16][ks], 24);
#pragma unroll
                for (int t = 0; t < af[i].num_elements; t++)
                    af[i].x[t] = wmma::__float_to_tf32(af[i].x[t]);
            }
#pragma unroll
            for (int j = 0; j < 2; j++) {
                wmma::load_matrix_sync(bf[j], &Bs[st][ks][wn * 32 + j * 16], 72);
#pragma unroll
                for (int t = 0; t < bf[j].num_elements; t++)
                    bf[j].x[t] = wmma::__float_to_tf32(bf[j].x[t]);
            }
#pragma unroll
            for (int i = 0; i < 2; i++)
#pragma unroll
                for (int j = 0; j < 2; j++)
                    wmma::mma_sync(acc[i][j], af[i], bf[j], acc[i][j]);
        }
        __syncthreads();
        st ^= 1;
    }

#pragma unroll
    for (int i = 0; i < 2; i++) {
        int r = rowBase + wm * 32 + i * 16;
        if (r < M) {   // M % 16 == 0 -> fragment fully valid
#pragma unroll
            for (int j = 0; j < 2; j++)
                wmma::store_matrix_sync(&C[(size_t)r * Nn + colBase + wn * 32 + j * 16],
                                        acc[i][j], Nn, wmma::mem_row_major);
        }
    }
}

// ---------------- layer1: attention + beta + relu, warp per node ------------
// Online softmax with 2 independent ILP chains, biases in-register,
// gated beta skip fused in epilogue. Writes h directly.
__global__ __launch_bounds__(256) void attn1_beta_kernel(
        const float* __restrict__ q, const float* __restrict__ k,
        const float* __restrict__ v, const float* __restrict__ rraw,
        const float* __restrict__ bq, const float* __restrict__ bk,
        const float* __restrict__ bv, const float* __restrict__ bs,
        const float* __restrict__ wb, float* __restrict__ h) {
    int n = (blockIdx.x * blockDim.x + threadIdx.x) >> 5;
    if (n >= N_NODES) return;
    int lane = threadIdx.x & 31;
    int col = lane * 8;

    float4 q0 = *reinterpret_cast<const float4*>(&q[(size_t)n * F1 + col]);
    float4 q1 = *reinterpret_cast<const float4*>(&q[(size_t)n * F1 + col + 4]);
    {
        float4 qb0 = *reinterpret_cast<const float4*>(&bq[col]);
        float4 qb1 = *reinterpret_cast<const float4*>(&bq[col + 4]);
        q0.x += qb0.x; q0.y += qb0.y; q0.z += qb0.z; q0.w += qb0.w;
        q1.x += qb1.x; q1.y += qb1.y; q1.z += qb1.z; q1.w += qb1.w;
    }
    float4 kb0 = *reinterpret_cast<const float4*>(&bk[col]);
    float4 kb1 = *reinterpret_cast<const float4*>(&bk[col + 4]);
    float4 vb0 = *reinterpret_cast<const float4*>(&bv[col]);
    float4 vb1 = *reinterpret_cast<const float4*>(&bv[col + 4]);

    int beg = g_off[n], end = g_off[n + 1];

    // two independent online-softmax chains
    float mA = -3.4e38f, sA = 0.f, mB = -3.4e38f, sB = 0.f;
    float4 aA0 = {0,0,0,0}, aA1 = {0,0,0,0}, aB0 = {0,0,0,0}, aB1 = {0,0,0,0};

    int i = beg;
    for (; i + 2 <= end; i += 2) {
        int s0 = g_csr_src[i], s1 = g_csr_src[i + 1];
        size_t b0 = (size_t)s0 * F1 + col, b1 = (size_t)s1 * F1 + col;
        float4 kA0 = *reinterpret_cast<const float4*>(&k[b0]);
        float4 kA1 = *reinterpret_cast<const float4*>(&k[b0 + 4]);
        float4 kB0 = *reinterpret_cast<const float4*>(&k[b1]);
        float4 kB1 = *reinterpret_cast<const float4*>(&k[b1 + 4]);
        float4 vA0 = *reinterpret_cast<const float4*>(&v[b0]);
        float4 vA1 = *reinterpret_cast<const float4*>(&v[b0 + 4]);
        float4 vB0 = *reinterpret_cast<const float4*>(&v[b1]);
        float4 vB1 = *reinterpret_cast<const float4*>(&v[b1 + 4]);

        float dA = q0.x*(kA0.x+kb0.x) + q0.y*(kA0.y+kb0.y) + q0.z*(kA0.z+kb0.z) + q0.w*(kA0.w+kb0.w)
                 + q1.x*(kA1.x+kb1.x) + q1.y*(kA1.y+kb1.y) + q1.z*(kA1.z+kb1.z) + q1.w*(kA1.w+kb1.w);
        float dB = q0.x*(kB0.x+kb0.x) + q0.y*(kB0.y+kb0.y) + q0.z*(kB0.z+kb0.z) + q0.w*(kB0.w+kb0.w)
                 + q1.x*(kB1.x+kb1.x) + q1.y*(kB1.y+kb1.y) + q1.z*(kB1.z+kb1.z) + q1.w*(kB1.w+kb1.w);
        dA += __shfl_xor_sync(0xFFFFFFFFu, dA, 1);
        dB += __shfl_xor_sync(0xFFFFFFFFu, dB, 1);
        dA += __shfl_xor_sync(0xFFFFFFFFu, dA, 2);
        dB += __shfl_xor_sync(0xFFFFFFFFu, dB, 2);
        dA += __shfl_xor_sync(0xFFFFFFFFu, dA, 4);
        dB += __shfl_xor_sync(0xFFFFFFFFu, dB, 4);
        dA *= 0.125f; dB *= 0.125f;

        float mnA = fmaxf(mA, dA), mnB = fmaxf(mB, dB);
        float cA = __expf(mA - mnA), cB = __expf(mB - mnB);
        float pA = __expf(dA - mnA), pB = __expf(dB - mnB);
        sA = sA * cA + pA; sB = sB * cB + pB;
        aA0.x = aA0.x*cA + pA*(vA0.x+vb0.x); aA0.y = aA0.y*cA + pA*(vA0.y+vb0.y);
        aA0.z = aA0.z*cA + pA*(vA0.z+vb0.z); aA0.w = aA0.w*cA + pA*(vA0.w+vb0.w);
        aA1.x = aA1.x*cA + pA*(vA1.x+vb1.x); aA1.y = aA1.y*cA + pA*(vA1.y+vb1.y);
        aA1.z = aA1.z*cA + pA*(vA1.z+vb1.z); aA1.w = aA1.w*cA + pA*(vA1.w+vb1.w);
        aB0.x = aB0.x*cB + pB*(vB0.x+vb0.x); aB0.y = aB0.y*cB + pB*(vB0.y+vb0.y);
        aB0.z = aB0.z*cB + pB*(vB0.z+vb0.z); aB0.w = aB0.w*cB + pB*(vB0.w+vb0.w);
        aB1.x = aB1.x*cB + pB*(vB1.x+vb1.x); aB1.y = aB1.y*cB + pB*(vB1.y+vb1.y);
        aB1.z = aB1.z*cB + pB*(vB1.z+vb1.z); aB1.w = aB1.w*cB + pB*(vB1.w+vb1.w);
        mA = mnA; mB = mnB;
    }
    if (i < end) {   // trailing edge -> chain A
        int s0 = g_csr_src[i];
        size_t b0 = (size_t)s0 * F1 + col;
        float4 kA0 = *reinterpret_cast<const float4*>(&k[b0]);
        float4 kA1 = *reinterpret_cast<const float4*>(&k[b0 + 4]);
        float4 vA0 = *reinterpret_cast<const float4*>(&v[b0]);
        float4 vA1 = *reinterpret_cast<const float4*>(&v[b0 + 4]);
        float dA = q0.x*(kA0.x+kb0.x) + q0.y*(kA0.y+kb0.y) + q0.z*(kA0.z+kb0.z) + q0.w*(kA0.w+kb0.w)
                 + q1.x*(kA1.x+kb1.x) + q1.y*(kA1.y+kb1.y) + q1.z*(kA1.z+kb1.z) + q1.w*(kA1.w+kb1.w);
        dA += __shfl_xor_sync(0xFFFFFFFFu, dA, 1);
        dA += __shfl_xor_sync(0xFFFFFFFFu, dA, 2);
        dA += __shfl_xor_sync(0xFFFFFFFFu, dA, 4);
        dA *= 0.125f;
        float mnA = fmaxf(mA, dA);
        float cA = __expf(mA - mnA), pA = __expf(dA - mnA);
        sA = sA * cA + pA;
        aA0.x = aA0.x*cA + pA*(vA0.x+vb0.x); aA0.y = aA0.y*cA + pA*(vA0.y+vb0.y);
        aA0.z = aA0.z*cA + pA*(vA0.z+vb0.z); aA0.w = aA0.w*cA + pA*(vA0.w+vb0.w);
        aA1.x = aA1.x*cA + pA*(vA1.x+vb1.x); aA1.y = aA1.y*cA + pA*(vA1.y+vb1.y);
        aA1.z = aA1.z*cA + pA*(vA1.z+vb1.z); aA1.w = aA1.w*cA + pA*(vA1.w+vb1.w);
        mA = mnA;
    }
    // merge chains
    float mn = fmaxf(mA, mB);
    float cA = __expf(mA - mn), cB = __expf(mB - mn);
    float ssum = sA * cA + sB * cB;
    float inv = 1.f / (ssum + 1e-16f);
    float o[8];
    o[0] = (aA0.x*cA + aB0.x*cB) * inv; o[1] = (aA0.y*cA + aB0.y*cB) * inv;
    o[2] = (aA0.z*cA + aB0.z*cB) * inv; o[3] = (aA0.w*cA + aB0.w*cB) * inv;
    o[4] = (aA1.x*cA + aB1.x*cB) * inv; o[5] = (aA1.y*cA + aB1.y*cB) * inv;
    o[6] = (aA1.z*cA + aB1.z*cB) * inv; o[7] = (aA1.w*cA + aB1.w*cB) * inv;

    // ---- fused gated beta skip + relu ----
    float rr[8];
    {
        float4 r0 = *reinterpret_cast<const float4*>(&rraw[(size_t)n * F1 + col]);
        float4 r1 = *reinterpret_cast<const float4*>(&rraw[(size_t)n * F1 + col + 4]);
        float4 sb0 = *reinterpret_cast<const float4*>(&bs[col]);
        float4 sb1 = *reinterpret_cast<const float4*>(&bs[col + 4]);
        rr[0] = r0.x + sb0.x; rr[1] = r0.y + sb0.y; rr[2] = r0.z + sb0.z; rr[3] = r0.w + sb0.w;
        rr[4] = r1.x + sb1.x; rr[5] = r1.y + sb1.y; rr[6] = r1.z + sb1.z; rr[7] = r1.w + sb1.w;
    }
    float s = 0.f;
#pragma unroll
    for (int u = 0; u < 8; u++) {
        int c = col + u;
        // o*wbA + r*wbB + (o-r)*wbC = o*(wbA+wbC) + r*(wbB-wbC)
        s += o[u] * (wb[c] + wb[2 * F1 + c]) + rr[u] * (wb[F1 + c] - wb[2 * F1 + c]);
    }
#pragma unroll
    for (int off = 16; off > 0; off >>= 1) s += __shfl_xor_sync(0xFFFFFFFFu, s, off);
    float beta = 1.f / (1.f + __expf(-s));
    float res[8];
#pragma unroll
    for (int u = 0; u < 8; u++)
        res[u] = fmaxf(beta * rr[u] + (1.f - beta) * o[u], 0.f);
    *reinterpret_cast<float4*>(&h[(size_t)n * F1 + col]) =
        make_float4(res[0], res[1], res[2], res[3]);
    *reinterpret_cast<float4*>(&h[(size_t)n * F1 + col + 4]) =
        make_float4(res[4], res[5], res[6], res[7]);
}

// ---------------- layer2: attention + beta + log_softmax, warp per node -----
__global__ __launch_bounds__(256) void attn2_lsm_kernel(
        const float* __restrict__ q, const float* __restrict__ k,
        const float* __restrict__ v, const float* __restrict__ rraw,
        const float* __restrict__ bq, const float* __restrict__ bk,
        const float* __restrict__ bv, const float* __restrict__ bs,
        const float* __restrict__ wb, float* __restrict__ ob, int dup) {
    int n = (blockIdx.x * blockDim.x + threadIdx.x) >> 5;
    if (n >= N_NODES) return;
    int lane = threadIdx.x & 31;
    int col = lane * 2;

    float2 qv = *reinterpret_cast<const float2*>(&q[(size_t)n * F2 + col]);
    {
        float2 qb = *reinterpret_cast<const float2*>(&bq[col]);
        qv.x += qb.x; qv.y += qb.y;
    }
    float2 kb = *reinterpret_cast<const float2*>(&bk[col]);
    float2 vb = *reinterpret_cast<const float2*>(&bv[col]);

    int beg = g_off[n], end = g_off[n + 1];
    float mA = -3.4e38f, sA = 0.f, mB = -3.4e38f, sB = 0.f;
    float aAx = 0.f, aAy = 0.f, aBx = 0.f, aBy = 0.f;

    int i = beg;
    for (; i + 2 <= end; i += 2) {
        int s0 = g_csr_src[i], s1 = g_csr_src[i + 1];
        float2 kA = *reinterpret_cast<const float2*>(&k[(size_t)s0 * F2 + col]);
        float2 kB = *reinterpret_cast<const float2*>(&k[(size_t)s1 * F2 + col]);
        float2 vA = *reinterpret_cast<const float2*>(&v[(size_t)s0 * F2 + col]);
        float2 vB = *reinterpret_cast<const float2*>(&v[(size_t)s1 * F2 + col]);
        float dA = qv.x * (kA.x + kb.x) + qv.y * (kA.y + kb.y);
        float dB = qv.x * (kB.x + kb.x) + qv.y * (kB.y + kb.y);
#pragma unroll
        for (int o = 16; o > 0; o >>= 1) {
            dA += __shfl_xor_sync(0xFFFFFFFFu, dA, o);
            dB += __shfl_xor_sync(0xFFFFFFFFu, dB, o);
        }
        dA *= 0.125f; dB *= 0.125f;
        float mnA = fmaxf(mA, dA), mnB = fmaxf(mB, dB);
        float cA = __expf(mA - mnA), cB = __expf(mB - mnB);
        float pA = __expf(dA - mnA), pB = __expf(dB - mnB);
        sA = sA * cA + pA; sB = sB * cB + pB;
        aAx = aAx * cA + pA * (vA.x + vb.x); aAy = aAy * cA + pA * (vA.y + vb.y);
        aBx = aBx * cB + pB * (vB.x + vb.x); aBy = aBy * cB + pB * (vB.y + vb.y);
        mA = mnA; mB = mnB;
    }
    if (i < end) {
        int s0 = g_csr_src[i];
        float2 kA = *reinterpret_cast<const float2*>(&k[(size_t)s0 * F2 + col]);
        float2 vA = *reinterpret_cast<const float2*>(&v[(size_t)s0 * F2 + col]);
        float dA = qv.x * (kA.x + kb.x) + qv.y * (kA.y + kb.y);
#pragma unroll
        for (int o = 16; o > 0; o >>= 1) dA += __shfl_xor_sync(0xFFFFFFFFu, dA, o);
        dA *= 0.125f;
        float mnA = fmaxf(mA, dA);
        float cA = __expf(mA - mnA), pA = __expf(dA - mnA);
        sA = sA * cA + pA;
        aAx = aAx * cA + pA * (vA.x + vb.x); aAy = aAy * cA + pA * (vA.y + vb.y);
        mA = mnA;
    }
    float mn = fmaxf(mA, mB);
    float cA = __expf(mA - mn), cB = __expf(mB - mn);
    float ssum = sA * cA + sB * cB;
    float inv = 1.f / (ssum + 1e-16f);
    float o0 = (aAx * cA + aBx * cB) * inv;
    float o1 = (aAy * cA + aBy * cB) * inv;

    // ---- fused gated beta skip ----
    float r0, r1;
    {
        float2 rv = *reinterpret_cast<const float2*>(&rraw[(size_t)n * F2 + col]);
        float2 bv2 = *reinterpret_cast<const float2*>(&bs[col]);
        r0 = rv.x + bv2.x; r1 = rv.y + bv2.y;
    }
    float s = o0 * (wb[col] + wb[2 * F2 + col]) + r0 * (wb[F2 + col] - wb[2 * F2 + col])
            + o1 * (wb[col + 1] + wb[2 * F2 + col + 1]) + r1 * (wb[F2 + col + 1] - wb[2 * F2 + col + 1]);
#pragma unroll
    for (int off = 16; off > 0; off >>= 1) s += __shfl_xor_sync(0xFFFFFFFFu, s, off);
    float beta = 1.f / (1.f + __expf(-s));
    float v0 = beta * r0 + (1.f - beta) * o0;
    float v1 = beta * r1 + (1.f - beta) * o1;

    // ---- log_softmax over the 64-wide row ----
    float m = fmaxf(v0, v1);
#pragma unroll
    for (int o = 16; o > 0; o >>= 1) m = fmaxf(m, __shfl_xor_sync(0xFFFFFFFFu, m, o));
    float es = expf(v0 - m) + expf(v1 - m);
#pragma unroll
    for (int o = 16; o > 0; o >>= 1) es += __shfl_xor_sync(0xFFFFFFFFu, es, o);
    float ls = m + logf(es);

    *reinterpret_cast<float2*>(&ob[(size_t)n * F2 + col]) = make_float2(v0 - ls, v1 - ls);
    if (dup) {
        size_t off = (size_t)N_NODES * F2;
        *reinterpret_cast<float2*>(&ob[off + (size_t)n * F2 + col]) = make_float2(v0, v1);
    }
}

// ---------------- host launcher ---------------------------------------------
extern "C" void kernel_launch(void* const* d_in, const int* in_sizes, int n_in,
                              void* d_out, int out_size) {
    const float* x   = (const float*)d_in[0];
    const int*   ei  = (const int*)d_in[1];
    const int*   src = ei;
    const int*   dst = ei + N_EDGES;

    const float* wq1 = (const float*)d_in[3];
    const float* bq1 = (const float*)d_in[4];
    const float* wk1 = (const float*)d_in[5];
    const float* bk1 = (const float*)d_in[6];
    const float* wv1 = (const float*)d_in[7];
    const float* bv1 = (const float*)d_in[8];
    const float* ws1 = (const float*)d_in[9];
    const float* bs1 = (const float*)d_in[10];
    const float* wb1 = (const float*)d_in[11];
    const float* wq2 = (const float*)d_in[12];
    const float* bq2 = (const float*)d_in[13];
    const float* wk2 = (const float*)d_in[14];
    const float* bk2 = (const float*)d_in[15];
    const float* wv2 = (const float*)d_in[16];
    const float* bv2 = (const float*)d_in[17];
    const float* ws2 = (const float*)d_in[18];
    const float* bs2 = (const float*)d_in[19];
    const float* wb2 = (const float*)d_in[20];

    float *q1, *k1, *v1, *r1, *h;
    float *q2, *k2, *v2, *r2;
    cudaGetSymbolAddress((void**)&q1, g_q1);
    cudaGetSymbolAddress((void**)&k1, g_k1);
    cudaGetSymbolAddress((void**)&v1, g_v1);
    cudaGetSymbolAddress((void**)&r1, g_r1);
    cudaGetSymbolAddress((void**)&h, g_h);
    cudaGetSymbolAddress((void**)&q2, g_q2);
    cudaGetSymbolAddress((void**)&k2, g_k2);
    cudaGetSymbolAddress((void**)&v2, g_v2);
    cudaGetSymbolAddress((void**)&r2, g_r2);

    // ---- CSR build ----
    deg_zero_kernel<<<(N_NODES + 255) / 256, 256>>>();
    deg_count_kernel<<<(N_EDGES + 255) / 256, 256>>>(dst);
    scan_kernel<<<1, 1024>>>();
    scatter_kernel<<<(N_EDGES + 255) / 256, 256>>>(src, dst);

    // ---- layer 1: 4 GEMMs in one launch (x shared) ----
    dim3 g1(F1 / 64, (N_NODES + 127) / 128, 4);
    gemm4_tf32<<<g1, 256>>>(x, wq1, wk1, wv1, ws1, q1, k1, v1, r1,
                            N_NODES, F1, IN_CH);

    attn1_beta_kernel<<<(N_NODES + 7) / 8, 256>>>(q1, k1, v1, r1,
                                                  bq1, bk1, bv1, bs1, wb1, h);

    // ---- layer 2: 4 GEMMs in one launch (h shared) ----
    dim3 g2(F2 / 64, (N_NODES + 127) / 128, 4);
    gemm4_tf32<<<g2, 256>>>(h, wq2, wk2, wv2, ws2, q2, k2, v2, r2,
                            N_NODES, F2, F1);

    int dup = (out_size >= 2 * N_NODES * F2) ? 1 : 0;
    attn2_lsm_kernel<<<(N_NODES + 7) / 8, 256>>>(q2, k2, v2, r2,
                                                 bq2, bk2, bv2, bs2, wb2,
                                                 (float*)d_out, dup);
}

// round 5
// speedup vs baseline: 3.5145x; 1.1161x over previous
#include <cuda_runtime.h>
#include <mma.h>
#include <math.h>
#include <stdint.h>

using namespace nvcuda;

#define N_NODES 50000
#define N_EDGES 800000
#define IN_CH   128
#define F1      256   // heads*out layer1
#define F2      64
#define H1      4

// ---------------- scratch (device globals; no allocation allowed) -----------
__device__ float g_q1[N_NODES * F1];
__device__ float g_k1[N_NODES * F1];
__device__ float g_v1[N_NODES * F1];
__device__ float g_r1[N_NODES * F1];
__device__ float g_h[N_NODES * F1];

__device__ float g_q2[N_NODES * F2];
__device__ float g_k2[N_NODES * F2];
__device__ float g_v2[N_NODES * F2];
__device__ float g_r2[N_NODES * F2];

// CSR scratch
#define SCAN_NBLK ((N_NODES + 1023) / 1024)   // 49
__device__ int g_deg[N_NODES];
__device__ int g_off[N_NODES + 1];
__device__ int g_pos[N_NODES];
__device__ int g_csr_src[N_EDGES];
__device__ int g_bsum[SCAN_NBLK];
__device__ int g_bscan[SCAN_NBLK];

// ---------------- cp.async helpers ------------------------------------------
__device__ __forceinline__ void cp_async16(uint32_t saddr, const void* gptr) {
    asm volatile("cp.async.cg.shared.global [%0], [%1], 16;\n"
                 :: "r"(saddr), "l"(gptr));
}
__device__ __forceinline__ void cp_commit() {
    asm volatile("cp.async.commit_group;\n");
}
template <int N>
__device__ __forceinline__ void cp_wait() {
    asm volatile("cp.async.wait_group %0;\n" :: "n"(N));
}

// ---------------- CSR build --------------------------------------------------
__global__ void deg_count_kernel(const int* __restrict__ dst) {
    int e = blockIdx.x * blockDim.x + threadIdx.x;
    if (e < N_EDGES) atomicAdd(&g_deg[dst[e]], 1);
}

// scan stage 1: 49 blocks x 256 threads, 4 elems/thread, coalesced.
// Writes element-exclusive prefix (within block) to g_off, block total to g_bsum.
__global__ void scan1_kernel() {
    __shared__ int ss[256];
    int t = threadIdx.x;
    int base = blockIdx.x * 1024 + t * 4;
    int d0 = (base     < N_NODES) ? g_deg[base]     : 0;
    int d1 = (base + 1 < N_NODES) ? g_deg[base + 1] : 0;
    int d2 = (base + 2 < N_NODES) ? g_deg[base + 2] : 0;
    int d3 = (base + 3 < N_NODES) ? g_deg[base + 3] : 0;
    int s = d0 + d1 + d2 + d3;
    ss[t] = s;
    __syncthreads();
    for (int off = 1; off < 256; off <<= 1) {
        int v = (t >= off) ? ss[t - off] : 0;
        __syncthreads();
        ss[t] += v;
        __syncthreads();
    }
    int ex = ss[t] - s;   // block-exclusive prefix for this thread's chunk
    int e0 = ex, e1 = ex + d0, e2 = e1 + d1, e3 = e2 + d2;
    if (base     < N_NODES) g_off[base]     = e0;
    if (base + 1 < N_NODES) g_off[base + 1] = e1;
    if (base + 2 < N_NODES) g_off[base + 2] = e2;
    if (base + 3 < N_NODES) g_off[base + 3] = e3;
    if (t == 255) g_bsum[blockIdx.x] = ss[255];
}

// scan stage 2: single block of 64, scan the 49 block sums.
__global__ void scan2_kernel() {
    __shared__ int ss[64];
    int t = threadIdx.x;
    int v = (t < SCAN_NBLK) ? g_bsum[t] : 0;
    ss[t] = v;
    __syncthreads();
    for (int off = 1; off < 64; off <<= 1) {
        int u = (t >= off) ? ss[t - off] : 0;
        __syncthreads();
        ss[t] += u;
        __syncthreads();
    }
    if (t < SCAN_NBLK) g_bscan[t] = ss[t] - v;        // exclusive
    if (t == SCAN_NBLK - 1) g_off[N_NODES] = ss[t];   // total = E
}

// scan stage 3: add block offsets; materialize g_pos.
__global__ void scan3_kernel() {
    int t = threadIdx.x;
    int add = g_bscan[blockIdx.x];
    int base = blockIdx.x * 1024 + t * 4;
#pragma unroll
    for (int i = 0; i < 4; i++) {
        int idx = base + i;
        if (idx < N_NODES) {
            int v = g_off[idx] + add;
            g_off[idx] = v;
            g_pos[idx] = v;
        }
    }
}

__global__ void scatter_kernel(const int* __restrict__ src, const int* __restrict__ dst) {
    int e = blockIdx.x * blockDim.x + threadIdx.x;
    if (e < N_EDGES) {
        int slot = atomicAdd(&g_pos[dst[e]], 1);
        g_csr_src[slot] = src[e];
    }
}

// ---------------- TF32 GEMM, BK=32, cp.async double-buffered -----------------
// C_z = A @ B_z (4 GEMMs share A via blockIdx.z). BM=128, BN=64, BK=32.
// 256 threads = 8 warps (4x2), warp tile 32x32 (wmma 16x16x8). No bias.
#define GEMM_SMEM ((2 * 128 * 36 + 2 * 32 * 68) * 4)   // 54272 bytes

__global__ __launch_bounds__(256) void gemm4_tf32(
        const float* __restrict__ A,
        const float* __restrict__ B0, const float* __restrict__ B1,
        const float* __restrict__ B2, const float* __restrict__ B3,
        float* __restrict__ C0, float* __restrict__ C1,
        float* __restrict__ C2, float* __restrict__ C3,
        int M, int Nn, int K) {
    const float* B;
    float* C;
    switch (blockIdx.z) {
        case 0: B = B0; C = C0; break;
        case 1: B = B1; C = C1; break;
        case 2: B = B2; C = C2; break;
        default: B = B3; C = C3; break;
    }

    extern __shared__ float dsm[];
    float (*As)[128][36] = reinterpret_cast<float(*)[128][36]>(dsm);
    float (*Bs)[32][68]  = reinterpret_cast<float(*)[32][68]>(dsm + 2 * 128 * 36);

    int tid = threadIdx.x;
    int warp = tid >> 5;
    int wm = warp & 3;
    int wn = warp >> 2;
    int rowBase = blockIdx.y * 128;
    int colBase = blockIdx.x * 64;

    int aRow = tid >> 3;        // 0..31
    int aCol = (tid & 7) * 4;   // 0..28
    int bRow = tid >> 4;        // 0..15
    int bCol = (tid & 15) * 4;  // 0..60

    int grA[4];
#pragma unroll
    for (int r = 0; r < 4; r++) {
        int rr = rowBase + aRow + r * 32;
        grA[r] = rr < M ? rr : M - 1;   // clamped rows never stored
    }

    uint32_t sA[2][4], sB[2][2];
#pragma unroll
    for (int st = 0; st < 2; st++) {
#pragma unroll
        for (int r = 0; r < 4; r++)
            sA[st][r] = (uint32_t)__cvta_generic_to_shared(&As[st][aRow + r * 32][aCol]);
#pragma unroll
        for (int r = 0; r < 2; r++)
            sB[st][r] = (uint32_t)__cvta_generic_to_shared(&Bs[st][bRow + r * 16][bCol]);
    }

    wmma::fragment<wmma::accumulator, 16, 16, 8, float> acc[2][2];
#pragma unroll
    for (int i = 0; i < 2; i++)
#pragma unroll
        for (int j = 0; j < 2; j++) wmma::fill_fragment(acc[i][j], 0.0f);

    // prologue: stage 0, k0 = 0
#pragma unroll
    for (int r = 0; r < 4; r++)
        cp_async16(sA[0][r], &A[(size_t)grA[r] * K + aCol]);
#pragma unroll
    for (int r = 0; r < 2; r++)
        cp_async16(sB[0][r], &B[(size_t)(bRow + r * 16) * Nn + colBase + bCol]);
    cp_commit();

    int st = 0;
    for (int k0 = 0; k0 < K; k0 += 32) {
        if (k0 + 32 < K) {
            int ns = st ^ 1;
#pragma unroll
            for (int r = 0; r < 4; r++)
                cp_async16(sA[ns][r], &A[(size_t)grA[r] * K + k0 + 32 + aCol]);
#pragma unroll
            for (int r = 0; r < 2; r++)
                cp_async16(sB[ns][r], &B[(size_t)(k0 + 32 + bRow + r * 16) * Nn + colBase + bCol]);
        }
        cp_commit();
        cp_wait<1>();
        __syncthreads();

#pragma unroll
        for (int ks = 0; ks < 32; ks += 8) {
            wmma::fragment<wmma::matrix_a, 16, 16, 8, wmma::precision::tf32, wmma::row_major> af[2];
            wmma::fragment<wmma::matrix_b, 16, 16, 8, wmma::precision::tf32, wmma::row_major> bf[2];
#pragma unroll
            for (int i = 0; i < 2; i++) {
                wmma::load_matrix_sync(af[i], &As[st][wm * 32 + i * 16][ks], 36);
#pragma unroll
                for (int t = 0; t < af[i].num_elements; t++)
                    af[i].x[t] = wmma::__float_to_tf32(af[i].x[t]);
            }
#pragma unroll
            for (int j = 0; j < 2; j++) {
                wmma::load_matrix_sync(bf[j], &Bs[st][ks][wn * 32 + j * 16], 68);
#pragma unroll
                for (int t = 0; t < bf[j].num_elements; t++)
                    bf[j].x[t] = wmma::__float_to_tf32(bf[j].x[t]);
            }
#pragma unroll
            for (int i = 0; i < 2; i++)
#pragma unroll
                for (int j = 0; j < 2; j++)
                    wmma::mma_sync(acc[i][j], af[i], bf[j], acc[i][j]);
        }
        __syncthreads();
        st ^= 1;
    }

#pragma unroll
    for (int i = 0; i < 2; i++) {
        int r = rowBase + wm * 32 + i * 16;
        if (r < M) {   // M % 16 == 0 -> fragment fully valid
#pragma unroll
            for (int j = 0; j < 2; j++)
                wmma::store_matrix_sync(&C[(size_t)r * Nn + colBase + wn * 32 + j * 16],
                                        acc[i][j], Nn, wmma::mem_row_major);
        }
    }
}

// ---------------- layer1: attention + beta + relu, warp per node ------------
__global__ __launch_bounds__(128) void attn1_beta_kernel(
        const float* __restrict__ q, const float* __restrict__ k,
        const float* __restrict__ v, const float* __restrict__ rraw,
        const float* __restrict__ bq, const float* __restrict__ bk,
        const float* __restrict__ bv, const float* __restrict__ bs,
        const float* __restrict__ wb, float* __restrict__ h) {
    int n = (blockIdx.x * blockDim.x + threadIdx.x) >> 5;
    if (n >= N_NODES) return;
    int lane = threadIdx.x & 31;
    int col = lane * 8;

    float4 q0 = *reinterpret_cast<const float4*>(&q[(size_t)n * F1 + col]);
    float4 q1 = *reinterpret_cast<const float4*>(&q[(size_t)n * F1 + col + 4]);
    {
        float4 qb0 = *reinterpret_cast<const float4*>(&bq[col]);
        float4 qb1 = *reinterpret_cast<const float4*>(&bq[col + 4]);
        q0.x += qb0.x; q0.y += qb0.y; q0.z += qb0.z; q0.w += qb0.w;
        q1.x += qb1.x; q1.y += qb1.y; q1.z += qb1.z; q1.w += qb1.w;
    }
    float4 kb0 = *reinterpret_cast<const float4*>(&bk[col]);
    float4 kb1 = *reinterpret_cast<const float4*>(&bk[col + 4]);
    float4 vb0 = *reinterpret_cast<const float4*>(&bv[col]);
    float4 vb1 = *reinterpret_cast<const float4*>(&bv[col + 4]);

    int beg = g_off[n], end = g_off[n + 1];

    float mA = -3.4e38f, sA = 0.f, mB = -3.4e38f, sB = 0.f;
    float4 aA0 = {0,0,0,0}, aA1 = {0,0,0,0}, aB0 = {0,0,0,0}, aB1 = {0,0,0,0};

    int i = beg;
    for (; i + 2 <= end; i += 2) {
        int s0 = g_csr_src[i], s1 = g_csr_src[i + 1];
        size_t b0 = (size_t)s0 * F1 + col, b1 = (size_t)s1 * F1 + col;
        float4 kA0 = *reinterpret_cast<const float4*>(&k[b0]);
        float4 kA1 = *reinterpret_cast<const float4*>(&k[b0 + 4]);
        float4 kB0 = *reinterpret_cast<const float4*>(&k[b1]);
        float4 kB1 = *reinterpret_cast<const float4*>(&k[b1 + 4]);
        float4 vA0 = *reinterpret_cast<const float4*>(&v[b0]);
        float4 vA1 = *reinterpret_cast<const float4*>(&v[b0 + 4]);
        float4 vB0 = *reinterpret_cast<const float4*>(&v[b1]);
        float4 vB1 = *reinterpret_cast<const float4*>(&v[b1 + 4]);

        float dA = q0.x*(kA0.x+kb0.x) + q0.y*(kA0.y+kb0.y) + q0.z*(kA0.z+kb0.z) + q0.w*(kA0.w+kb0.w)
                 + q1.x*(kA1.x+kb1.x) + q1.y*(kA1.y+kb1.y) + q1.z*(kA1.z+kb1.z) + q1.w*(kA1.w+kb1.w);
        float dB = q0.x*(kB0.x+kb0.x) + q0.y*(kB0.y+kb0.y) + q0.z*(kB0.z+kb0.z) + q0.w*(kB0.w+kb0.w)
                 + q1.x*(kB1.x+kb1.x) + q1.y*(kB1.y+kb1.y) + q1.z*(kB1.z+kb1.z) + q1.w*(kB1.w+kb1.w);
        dA += __shfl_xor_sync(0xFFFFFFFFu, dA, 1);
        dB += __shfl_xor_sync(0xFFFFFFFFu, dB, 1);
        dA += __shfl_xor_sync(0xFFFFFFFFu, dA, 2);
        dB += __shfl_xor_sync(0xFFFFFFFFu, dB, 2);
        dA += __shfl_xor_sync(0xFFFFFFFFu, dA, 4);
        dB += __shfl_xor_sync(0xFFFFFFFFu, dB, 4);
        dA *= 0.125f; dB *= 0.125f;

        float mnA = fmaxf(mA, dA), mnB = fmaxf(mB, dB);
        float cA = __expf(mA - mnA), cB = __expf(mB - mnB);
        float pA = __expf(dA - mnA), pB = __expf(dB - mnB);
        sA = sA * cA + pA; sB = sB * cB + pB;
        aA0.x = aA0.x*cA + pA*(vA0.x+vb0.x); aA0.y = aA0.y*cA + pA*(vA0.y+vb0.y);
        aA0.z = aA0.z*cA + pA*(vA0.z+vb0.z); aA0.w = aA0.w*cA + pA*(vA0.w+vb0.w);
        aA1.x = aA1.x*cA + pA*(vA1.x+vb1.x); aA1.y = aA1.y*cA + pA*(vA1.y+vb1.y);
        aA1.z = aA1.z*cA + pA*(vA1.z+vb1.z); aA1.w = aA1.w*cA + pA*(vA1.w+vb1.w);
        aB0.x = aB0.x*cB + pB*(vB0.x+vb0.x); aB0.y = aB0.y*cB + pB*(vB0.y+vb0.y);
        aB0.z = aB0.z*cB + pB*(vB0.z+vb0.z); aB0.w = aB0.w*cB + pB*(vB0.w+vb0.w);
        aB1.x = aB1.x*cB + pB*(vB1.x+vb1.x); aB1.y = aB1.y*cB + pB*(vB1.y+vb1.y);
        aB1.z = aB1.z*cB + pB*(vB1.z+vb1.z); aB1.w = aB1.w*cB + pB*(vB1.w+vb1.w);
        mA = mnA; mB = mnB;
    }
    if (i < end) {
        int s0 = g_csr_src[i];
        size_t b0 = (size_t)s0 * F1 + col;
        float4 kA0 = *reinterpret_cast<const float4*>(&k[b0]);
        float4 kA1 = *reinterpret_cast<const float4*>(&k[b0 + 4]);
        float4 vA0 = *reinterpret_cast<const float4*>(&v[b0]);
        float4 vA1 = *reinterpret_cast<const float4*>(&v[b0 + 4]);
        float dA = q0.x*(kA0.x+kb0.x) + q0.y*(kA0.y+kb0.y) + q0.z*(kA0.z+kb0.z) + q0.w*(kA0.w+kb0.w)
                 + q1.x*(kA1.x+kb1.x) + q1.y*(kA1.y+kb1.y) + q1.z*(kA1.z+kb1.z) + q1.w*(kA1.w+kb1.w);
        dA += __shfl_xor_sync(0xFFFFFFFFu, dA, 1);
        dA += __shfl_xor_sync(0xFFFFFFFFu, dA, 2);
        dA += __shfl_xor_sync(0xFFFFFFFFu, dA, 4);
        dA *= 0.125f;
        float mnA = fmaxf(mA, dA);
        float cA = __expf(mA - mnA), pA = __expf(dA - mnA);
        sA = sA * cA + pA;
        aA0.x = aA0.x*cA + pA*(vA0.x+vb0.x); aA0.y = aA0.y*cA + pA*(vA0.y+vb0.y);
        aA0.z = aA0.z*cA + pA*(vA0.z+vb0.z); aA0.w = aA0.w*cA + pA*(vA0.w+vb0.w);
        aA1.x = aA1.x*cA + pA*(vA1.x+vb1.x); aA1.y = aA1.y*cA + pA*(vA1.y+vb1.y);
        aA1.z = aA1.z*cA + pA*(vA1.z+vb1.z); aA1.w = aA1.w*cA + pA*(vA1.w+vb1.w);
        mA = mnA;
    }
    float mn = fmaxf(mA, mB);
    float cA = __expf(mA - mn), cB = __expf(mB - mn);
    float ssum = sA * cA + sB * cB;
    float inv = 1.f / (ssum + 1e-16f);
    float o[8];
    o[0] = (aA0.x*cA + aB0.x*cB) * inv; o[1] = (aA0.y*cA + aB0.y*cB) * inv;
    o[2] = (aA0.z*cA + aB0.z*cB) * inv; o[3] = (aA0.w*cA + aB0.w*cB) * inv;
    o[4] = (aA1.x*cA + aB1.x*cB) * inv; o[5] = (aA1.y*cA + aB1.y*cB) * inv;
    o[6] = (aA1.z*cA + aB1.z*cB) * inv; o[7] = (aA1.w*cA + aB1.w*cB) * inv;

    float rr[8];
    {
        float4 r0 = *reinterpret_cast<const float4*>(&rraw[(size_t)n * F1 + col]);
        float4 r1 = *reinterpret_cast<const float4*>(&rraw[(size_t)n * F1 + col + 4]);
        float4 sb0 = *reinterpret_cast<const float4*>(&bs[col]);
        float4 sb1 = *reinterpret_cast<const float4*>(&bs[col + 4]);
        rr[0] = r0.x + sb0.x; rr[1] = r0.y + sb0.y; rr[2] = r0.z + sb0.z; rr[3] = r0.w + sb0.w;
        rr[4] = r1.x + sb1.x; rr[5] = r1.y + sb1.y; rr[6] = r1.z + sb1.z; rr[7] = r1.w + sb1.w;
    }
    float s = 0.f;
#pragma unroll
    for (int u = 0; u < 8; u++) {
        int c = col + u;
        s += o[u] * (wb[c] + wb[2 * F1 + c]) + rr[u] * (wb[F1 + c] - wb[2 * F1 + c]);
    }
#pragma unroll
    for (int off = 16; off > 0; off >>= 1) s += __shfl_xor_sync(0xFFFFFFFFu, s, off);
    float beta = 1.f / (1.f + __expf(-s));
    float res[8];
#pragma unroll
    for (int u = 0; u < 8; u++)
        res[u] = fmaxf(beta * rr[u] + (1.f - beta) * o[u], 0.f);
    *reinterpret_cast<float4*>(&h[(size_t)n * F1 + col]) =
        make_float4(res[0], res[1], res[2], res[3]);
    *reinterpret_cast<float4*>(&h[(size_t)n * F1 + col + 4]) =
        make_float4(res[4], res[5], res[6], res[7]);
}

// ---------------- layer2: attention + beta + log_softmax --------------------
__global__ __launch_bounds__(128) void attn2_lsm_kernel(
        const float* __restrict__ q, const float* __restrict__ k,
        const float* __restrict__ v, const float* __restrict__ rraw,
        const float* __restrict__ bq, const float* __restrict__ bk,
        const float* __restrict__ bv, const float* __restrict__ bs,
        const float* __restrict__ wb, float* __restrict__ ob, int dup) {
    int n = (blockIdx.x * blockDim.x + threadIdx.x) >> 5;
    if (n >= N_NODES) return;
    int lane = threadIdx.x & 31;
    int col = lane * 2;

    float2 qv = *reinterpret_cast<const float2*>(&q[(size_t)n * F2 + col]);
    {
        float2 qb = *reinterpret_cast<const float2*>(&bq[col]);
        qv.x += qb.x; qv.y += qb.y;
    }
    float2 kb = *reinterpret_cast<const float2*>(&bk[col]);
    float2 vb = *reinterpret_cast<const float2*>(&bv[col]);

    int beg = g_off[n], end = g_off[n + 1];
    float mA = -3.4e38f, sA = 0.f, mB = -3.4e38f, sB = 0.f;
    float aAx = 0.f, aAy = 0.f, aBx = 0.f, aBy = 0.f;

    int i = beg;
    for (; i + 2 <= end; i += 2) {
        int s0 = g_csr_src[i], s1 = g_csr_src[i + 1];
        float2 kA = *reinterpret_cast<const float2*>(&k[(size_t)s0 * F2 + col]);
        float2 kB = *reinterpret_cast<const float2*>(&k[(size_t)s1 * F2 + col]);
        float2 vA = *reinterpret_cast<const float2*>(&v[(size_t)s0 * F2 + col]);
        float2 vB = *reinterpret_cast<const float2*>(&v[(size_t)s1 * F2 + col]);
        float dA = qv.x * (kA.x + kb.x) + qv.y * (kA.y + kb.y);
        float dB = qv.x * (kB.x + kb.x) + qv.y * (kB.y + kb.y);
#pragma unroll
        for (int o = 16; o > 0; o >>= 1) {
            dA += __shfl_xor_sync(0xFFFFFFFFu, dA, o);
            dB += __shfl_xor_sync(0xFFFFFFFFu, dB, o);
        }
        dA *= 0.125f; dB *= 0.125f;
        float mnA = fmaxf(mA, dA), mnB = fmaxf(mB, dB);
        float cA = __expf(mA - mnA), cB = __expf(mB - mnB);
        float pA = __expf(dA - mnA), pB = __expf(dB - mnB);
        sA = sA * cA + pA; sB = sB * cB + pB;
        aAx = aAx * cA + pA * (vA.x + vb.x); aAy = aAy * cA + pA * (vA.y + vb.y);
        aBx = aBx * cB + pB * (vB.x + vb.x); aBy = aBy * cB + pB * (vB.y + vb.y);
        mA = mnA; mB = mnB;
    }
    if (i < end) {
        int s0 = g_csr_src[i];
        float2 kA = *reinterpret_cast<const float2*>(&k[(size_t)s0 * F2 + col]);
        float2 vA = *reinterpret_cast<const float2*>(&v[(size_t)s0 * F2 + col]);
        float dA = qv.x * (kA.x + kb.x) + qv.y * (kA.y + kb.y);
#pragma unroll
        for (int o = 16; o > 0; o >>= 1) dA += __shfl_xor_sync(0xFFFFFFFFu, dA, o);
        dA *= 0.125f;
        float mnA = fmaxf(mA, dA);
        float cA = __expf(mA - mnA), pA = __expf(dA - mnA);
        sA = sA * cA + pA;
        aAx = aAx * cA + pA * (vA.x + vb.x); aAy = aAy * cA + pA * (vA.y + vb.y);
        mA = mnA;
    }
    float mn = fmaxf(mA, mB);
    float cA = __expf(mA - mn), cB = __expf(mB - mn);
    float ssum = sA * cA + sB * cB;
    float inv = 1.f / (ssum + 1e-16f);
    float o0 = (aAx * cA + aBx * cB) * inv;
    float o1 = (aAy * cA + aBy * cB) * inv;

    float r0, r1;
    {
        float2 rv = *reinterpret_cast<const float2*>(&rraw[(size_t)n * F2 + col]);
        float2 bv2 = *reinterpret_cast<const float2*>(&bs[col]);
        r0 = rv.x + bv2.x; r1 = rv.y + bv2.y;
    }
    float s = o0 * (wb[col] + wb[2 * F2 + col]) + r0 * (wb[F2 + col] - wb[2 * F2 + col])
            + o1 * (wb[col + 1] + wb[2 * F2 + col + 1]) + r1 * (wb[F2 + col + 1] - wb[2 * F2 + col + 1]);
#pragma unroll
    for (int off = 16; off > 0; off >>= 1) s += __shfl_xor_sync(0xFFFFFFFFu, s, off);
    float beta = 1.f / (1.f + __expf(-s));
    float v0 = beta * r0 + (1.f - beta) * o0;
    float v1 = beta * r1 + (1.f - beta) * o1;

    float m = fmaxf(v0, v1);
#pragma unroll
    for (int o = 16; o > 0; o >>= 1) m = fmaxf(m, __shfl_xor_sync(0xFFFFFFFFu, m, o));
    float es = expf(v0 - m) + expf(v1 - m);
#pragma unroll
    for (int o = 16; o > 0; o >>= 1) es += __shfl_xor_sync(0xFFFFFFFFu, es, o);
    float ls = m + logf(es);

    *reinterpret_cast<float2*>(&ob[(size_t)n * F2 + col]) = make_float2(v0 - ls, v1 - ls);
    if (dup) {
        size_t off = (size_t)N_NODES * F2;
        *reinterpret_cast<float2*>(&ob[off + (size_t)n * F2 + col]) = make_float2(v0, v1);
    }
}

// ---------------- host launcher ---------------------------------------------
extern "C" void kernel_launch(void* const* d_in, const int* in_sizes, int n_in,
                              void* d_out, int out_size) {
    const float* x   = (const float*)d_in[0];
    const int*   ei  = (const int*)d_in[1];
    const int*   src = ei;
    const int*   dst = ei + N_EDGES;

    const float* wq1 = (const float*)d_in[3];
    const float* bq1 = (const float*)d_in[4];
    const float* wk1 = (const float*)d_in[5];
    const float* bk1 = (const float*)d_in[6];
    const float* wv1 = (const float*)d_in[7];
    const float* bv1 = (const float*)d_in[8];
    const float* ws1 = (const float*)d_in[9];
    const float* bs1 = (const float*)d_in[10];
    const float* wb1 = (const float*)d_in[11];
    const float* wq2 = (const float*)d_in[12];
    const float* bq2 = (const float*)d_in[13];
    const float* wk2 = (const float*)d_in[14];
    const float* bk2 = (const float*)d_in[15];
    const float* wv2 = (const float*)d_in[16];
    const float* bv2 = (const float*)d_in[17];
    const float* ws2 = (const float*)d_in[18];
    const float* bs2 = (const float*)d_in[19];
    const float* wb2 = (const float*)d_in[20];

    float *q1, *k1, *v1, *r1, *h;
    float *q2, *k2, *v2, *r2;
    int *degp;
    cudaGetSymbolAddress((void**)&q1, g_q1);
    cudaGetSymbolAddress((void**)&k1, g_k1);
    cudaGetSymbolAddress((void**)&v1, g_v1);
    cudaGetSymbolAddress((void**)&r1, g_r1);
    cudaGetSymbolAddress((void**)&h, g_h);
    cudaGetSymbolAddress((void**)&q2, g_q2);
    cudaGetSymbolAddress((void**)&k2, g_k2);
    cudaGetSymbolAddress((void**)&v2, g_v2);
    cudaGetSymbolAddress((void**)&r2, g_r2);
    cudaGetSymbolAddress((void**)&degp, g_deg);

    cudaFuncSetAttribute(gemm4_tf32, cudaFuncAttributeMaxDynamicSharedMemorySize,
                         GEMM_SMEM);

    // ---- CSR build (coalesced 3-stage scan) ----
    cudaMemsetAsync(degp, 0, N_NODES * sizeof(int));
    deg_count_kernel<<<(N_EDGES + 255) / 256, 256>>>(dst);
    scan1_kernel<<<SCAN_NBLK, 256>>>();
    scan2_kernel<<<1, 64>>>();
    scan3_kernel<<<SCAN_NBLK, 256>>>();
    scatter_kernel<<<(N_EDGES + 255) / 256, 256>>>(src, dst);

    // ---- layer 1: 4 GEMMs in one launch (x shared) ----
    dim3 g1(F1 / 64, (N_NODES + 127) / 128, 4);
    gemm4_tf32<<<g1, 256, GEMM_SMEM>>>(x, wq1, wk1, wv1, ws1, q1, k1, v1, r1,
                                       N_NODES, F1, IN_CH);

    attn1_beta_kernel<<<(N_NODES + 3) / 4, 128>>>(q1, k1, v1, r1,
                                                  bq1, bk1, bv1, bs1, wb1, h);

    // ---- layer 2: 4 GEMMs in one launch (h shared) ----
    dim3 g2(F2 / 64, (N_NODES + 127) / 128, 4);
    gemm4_tf32<<<g2, 256, GEMM_SMEM>>>(h, wq2, wk2, wv2, ws2, q2, k2, v2, r2,
                                       N_NODES, F2, F1);

    int dup = (out_size >= 2 * N_NODES * F2) ? 1 : 0;
    attn2_lsm_kernel<<<(N_NODES + 3) / 4, 128>>>(q2, k2, v2, r2,
                                                 bq2, bk2, bv2, bs2, wb2,
                                                 (float*)d_out, dup);
}